// round 9
// baseline (speedup 1.0000x reference)
#include <cuda_runtime.h>
#include <cuda_fp16.h>
#include <math.h>

// ---------------------------------------------------------------------------
// Fused Haar-DWT -> conv1x1 QKV (fp16 mma.m16n8k16, fp32 accum) -> 2x2-window
// channel-attention (fp32, online softmax) -> Haar-IDWT.
// x (8,64,256,256) f32; w_qkv_lh (192,64); w_qkv_m (384,128).
//
// R9: attention lane remap — head (and band) folded into lanes so k/v LDS
// wavefronts carry 4-8 distinct rows (64-128B useful vs 16-32B broadcast).
// Online softmax accumulation (no p[] array). One attention call per phase.
// 72 KB SMEM, 256 threads, 3 CTAs/SM.
// ---------------------------------------------------------------------------

#define NTH  256
#define STH  264            // sub_t row stride (halves); 132 words == 4 mod 32
#define QP   36             // qkv row stride (floats)

#define SUBT_BYTES  (32 * STH * 2)          // 16896
#define QKV_FLOATS  (384 * QP)              // 13824
#define SMEM_BYTES  (SUBT_BYTES + QKV_FLOATS * 4)   // 72192

// qkv swizzle: q-load spread from row>>2, C-store decorrelation from row&3
#define QIDX(row, col) ((row) * QP + \
    (((col) ^ ((((row) >> 2) & 7) << 2)) ^ (((row) & 3) << 3)))

// fragment-ordered fp16 weight images: tile(M16,K16) x 32 lanes x uint4
__device__ uint4 g_wfrag_lh[12 * 4 * 32];
__device__ uint4 g_wfrag_m [24 * 8 * 32];

__device__ __forceinline__ unsigned pack2(float a, float b) {
    __half2 h = __floats2half2_rn(a, b);   // .x (low) = a
    return *(unsigned*)&h;
}
__device__ __forceinline__ float ex2f(float x) {
    float r; asm("ex2.approx.ftz.f32 %0, %1;" : "=f"(r) : "f"(x)); return r;
}
__device__ __forceinline__ float rcpf(float x) {
    float r; asm("rcp.approx.ftz.f32 %0, %1;" : "=f"(r) : "f"(x)); return r;
}

// scale * log2(e)
#define SC2_LH  0.36067376022224085f   // 0.25      * log2(e)
#define SC2_M   0.25505003980080184f   // 0.1767767 * log2(e)

// D += A(16x16,row) * B(16x8,col), fp16 in, fp32 accum
__device__ __forceinline__ void mma16(float* d, const uint4 a, unsigned b0, unsigned b1) {
    asm volatile(
        "mma.sync.aligned.m16n8k16.row.col.f32.f16.f16.f32 "
        "{%0,%1,%2,%3}, {%4,%5,%6,%7}, {%8,%9}, {%0,%1,%2,%3};"
        : "+f"(d[0]), "+f"(d[1]), "+f"(d[2]), "+f"(d[3])
        : "r"(a.x), "r"(a.y), "r"(a.z), "r"(a.w), "r"(b0), "r"(b1));
}

// ---------------------------------------------------------------------------
// prep: fragment-order the weights in fp16.
// ---------------------------------------------------------------------------
__global__ void prep_weights(const float* __restrict__ w_lh,
                             const float* __restrict__ w_m)
{
    const int i = blockIdx.x * blockDim.x + threadIdx.x;
    const int lane = i & 31;
    const int g = lane >> 2, t = lane & 3;
    if (i < 12 * 4 * 32) {
        const int T = i >> 5;
        const int kk = T & 3, mt = T >> 2;
        const int m = mt * 16 + g, k = kk * 16 + 2 * t;
        uint4 v;
        v.x = pack2(w_lh[m * 64 + k],           w_lh[m * 64 + k + 1]);
        v.y = pack2(w_lh[(m + 8) * 64 + k],     w_lh[(m + 8) * 64 + k + 1]);
        v.z = pack2(w_lh[m * 64 + k + 8],       w_lh[m * 64 + k + 9]);
        v.w = pack2(w_lh[(m + 8) * 64 + k + 8], w_lh[(m + 8) * 64 + k + 9]);
        g_wfrag_lh[T * 32 + lane] = v;
    } else {
        const int j = i - 12 * 4 * 32;
        if (j < 24 * 8 * 32) {
            const int T = j >> 5;
            const int kk = T & 7, mt = T >> 3;
            const int m = mt * 16 + g, k = kk * 16 + 2 * t;
            uint4 v;
            v.x = pack2(w_m[m * 128 + k],           w_m[m * 128 + k + 1]);
            v.y = pack2(w_m[(m + 8) * 128 + k],     w_m[(m + 8) * 128 + k + 1]);
            v.z = pack2(w_m[m * 128 + k + 8],       w_m[m * 128 + k + 9]);
            v.w = pack2(w_m[(m + 8) * 128 + k + 8], w_m[(m + 8) * 128 + k + 9]);
            g_wfrag_m[T * 32 + lane] = v;
        }
    }
}

// ---------------------------------------------------------------------------
// low+high attention, all heads+bands in one call.
// lane = (band, head, j): band=lane>>4, hd=(lane>>2)&3, j=lane&3.
// Each lane: 4 q-rows r = j+4i. k/v loads hit 8 distinct rows per warp.
// ---------------------------------------------------------------------------
__device__ __forceinline__ void attn_lh(
    const float* __restrict__ qkv, __half* __restrict__ subt,
    int wi, int lane)
{
    const int c0 = wi * 4;
    const int qb = (lane >> 4) * 192;          // 0 (low) or 192 (high)
    const int hd = (lane >> 2) & 3;
    const int j  = lane & 3;

    float4 q[4];
#pragma unroll
    for (int i = 0; i < 4; ++i)
        q[i] = *(const float4*)&qkv[QIDX(qb + (j + 4 * i) * 4 + hd, c0)];

    float sm[4] = {0.f, 0.f, 0.f, 0.f};
    float o[4][4];
#pragma unroll
    for (int i = 0; i < 4; ++i)
        o[i][0] = o[i][1] = o[i][2] = o[i][3] = 0.f;

#pragma unroll 8
    for (int d = 0; d < 16; ++d) {
        const float4 k4 = *(const float4*)&qkv[QIDX(qb + 64  + d * 4 + hd, c0)];
        const float4 v4 = *(const float4*)&qkv[QIDX(qb + 128 + d * 4 + hd, c0)];
#pragma unroll
        for (int i = 0; i < 4; ++i) {
            const float p = ex2f((q[i].x * k4.x + q[i].y * k4.y +
                                  q[i].z * k4.z + q[i].w * k4.w) * SC2_LH);
            sm[i] += p;
            o[i][0] = fmaf(p, v4.x, o[i][0]);
            o[i][1] = fmaf(p, v4.y, o[i][1]);
            o[i][2] = fmaf(p, v4.z, o[i][2]);
            o[i][3] = fmaf(p, v4.w, o[i][3]);
        }
    }
#pragma unroll
    for (int i = 0; i < 4; ++i) {
        const float inv = rcpf(sm[i]);
        const int ch = qb + (j + 4 * i) * 4 + hd;
#pragma unroll
        for (int pos = 0; pos < 4; ++pos)
            subt[(pos * 8 + wi) * STH + ch] = __float2half_rn(o[i][pos] * inv);
    }
}

// ---------------------------------------------------------------------------
// mid attention, all heads in one call.
// lane = (head, j): hd=lane>>3, j=lane&7. Each lane: 4 q-rows r = j+8i.
// k/v loads hit 4 distinct rows per warp (64B useful per wavefront).
// ---------------------------------------------------------------------------
__device__ __forceinline__ void attn_mid(
    const float* __restrict__ qkv, __half* __restrict__ subt,
    int wi, int lane)
{
    const int c0 = wi * 4;
    const int hd = lane >> 3;
    const int j  = lane & 7;

    float4 q[4];
#pragma unroll
    for (int i = 0; i < 4; ++i)
        q[i] = *(const float4*)&qkv[QIDX((j + 8 * i) * 4 + hd, c0)];

    float sm[4] = {0.f, 0.f, 0.f, 0.f};
    float o[4][4];
#pragma unroll
    for (int i = 0; i < 4; ++i)
        o[i][0] = o[i][1] = o[i][2] = o[i][3] = 0.f;

#pragma unroll 8
    for (int d = 0; d < 32; ++d) {
        const float4 k4 = *(const float4*)&qkv[QIDX(128 + d * 4 + hd, c0)];
        const float4 v4 = *(const float4*)&qkv[QIDX(256 + d * 4 + hd, c0)];
#pragma unroll
        for (int i = 0; i < 4; ++i) {
            const float p = ex2f((q[i].x * k4.x + q[i].y * k4.y +
                                  q[i].z * k4.z + q[i].w * k4.w) * SC2_M);
            sm[i] += p;
            o[i][0] = fmaf(p, v4.x, o[i][0]);
            o[i][1] = fmaf(p, v4.y, o[i][1]);
            o[i][2] = fmaf(p, v4.z, o[i][2]);
            o[i][3] = fmaf(p, v4.w, o[i][3]);
        }
    }
#pragma unroll
    for (int i = 0; i < 4; ++i) {
        const float inv = rcpf(sm[i]);
        const int ch = 64 + (j + 8 * i) * 4 + hd;
#pragma unroll
        for (int pos = 0; pos < 4; ++pos)
            subt[(pos * 8 + wi) * STH + ch] = __float2half_rn(o[i][pos] * inv);
    }
}

// ---------------------------------------------------------------------------
__global__ void __launch_bounds__(NTH, 3)
wavelet_attn_kernel(const float* __restrict__ x,
                    float* __restrict__ y)
{
    extern __shared__ char smem[];
    __half* subt = (__half*)smem;                       // 32 x STH halves
    float*  qkv  = (float*)(smem + SUBT_BYTES);         // 384 x QP floats

    const int tid  = threadIdx.x;
    const int wblk = blockIdx.x;       // 0..7
    const int h    = blockIdx.y;       // 0..63
    const int b    = blockIdx.z;       // 0..7

    const int warp = tid >> 5, lane = tid & 31;
    const int g = lane >> 2, t = lane & 3;

    const int xrow0 = 4 * h;
    const int xcol0 = 32 * wblk;
    const float* xb = x + (size_t)(b * 64) * 65536;

    // -------- phase 0: load x (float4), DWT -> sub_t (fp16, permuted rows) --
    {
        const int jq = tid & 7;
        const int ch = (tid >> 3) * 2;
        const float* xcA = xb + (size_t)ch * 65536;
        const float* xcB = xcA + 65536;
        const int col = xcol0 + 4 * jq;
#pragma unroll
        for (int dy = 0; dy < 2; ++dy) {
            const int r0 = xrow0 + 2 * dy;
            const float4 tA = *(const float4*)(xcA + r0 * 256 + col);
            const float4 uA = *(const float4*)(xcA + (r0 + 1) * 256 + col);
            const float4 tB = *(const float4*)(xcB + r0 * 256 + col);
            const float4 uB = *(const float4*)(xcB + (r0 + 1) * 256 + col);
#pragma unroll
            for (int dx = 0; dx < 2; ++dx) {
                const float aA = dx ? tA.z : tA.x, bA = dx ? tA.w : tA.y;
                const float cA = dx ? uA.z : uA.x, dA = dx ? uA.w : uA.y;
                const float aB = dx ? tB.z : tB.x, bB = dx ? tB.w : tB.y;
                const float cB = dx ? uB.z : uB.x, dB = dx ? uB.w : uB.y;
                const int row = (2 * dy + dx) * 8 + jq;
                __half* sr = &subt[row * STH + ch];
                *(unsigned*)&sr[0]   = pack2(( aA + bA + cA + dA) * 0.5f,
                                             ( aB + bB + cB + dB) * 0.5f);  // ll
                *(unsigned*)&sr[64]  = pack2((-aA - bA + cA + dA) * 0.5f,
                                             (-aB - bB + cB + dB) * 0.5f);  // lh
                *(unsigned*)&sr[128] = pack2((-aA + bA - cA + dA) * 0.5f,
                                             (-aB + bB - cB + dB) * 0.5f);  // hl
                *(unsigned*)&sr[192] = pack2(( aA - bA - cA + dA) * 0.5f,
                                             ( aB - bB - cB + dB) * 0.5f);  // hh
            }
        }
    }
    __syncthreads();

    // ======== fused LOW+HIGH GEMM (one pass over w_lh fragments) ========
    {
        const int wm = warp >> 1, wn = warp & 1;   // 4x2 warp grid
        float acc[2][3][2][4];
#pragma unroll
        for (int bd = 0; bd < 2; ++bd)
#pragma unroll
            for (int mt = 0; mt < 3; ++mt)
#pragma unroll
                for (int nt = 0; nt < 2; ++nt)
                    acc[bd][mt][nt][0] = acc[bd][mt][nt][1] =
                    acc[bd][mt][nt][2] = acc[bd][mt][nt][3] = 0.f;

#pragma unroll
        for (int kk = 0; kk < 4; ++kk) {
            uint4 af[3];
#pragma unroll
            for (int mt = 0; mt < 3; ++mt)
                af[mt] = g_wfrag_lh[((wm * 3 + mt) * 4 + kk) * 32 + lane];

            unsigned bl[2][2], bh[2][2];
            const int kcol = kk * 16 + 2 * t;
#pragma unroll
            for (int nt = 0; nt < 2; ++nt) {
                const int row = (wn * 2 + nt) * 8 + g;
                const __half* sr = &subt[row * STH + kcol];
                bl[nt][0] = *(const unsigned*)&sr[0];
                bl[nt][1] = *(const unsigned*)&sr[8];
                bh[nt][0] = *(const unsigned*)&sr[192];
                bh[nt][1] = *(const unsigned*)&sr[200];
            }
#pragma unroll
            for (int mt = 0; mt < 3; ++mt)
#pragma unroll
                for (int nt = 0; nt < 2; ++nt) {
                    mma16(acc[0][mt][nt], af[mt], bl[nt][0], bl[nt][1]);
                    mma16(acc[1][mt][nt], af[mt], bh[nt][0], bh[nt][1]);
                }
        }
        // C store (un-permute rows -> pos cols): n=2t -> pos 8t+2wn+nt; n+1 -> +4
#pragma unroll
        for (int bd = 0; bd < 2; ++bd)
#pragma unroll
            for (int mt = 0; mt < 3; ++mt) {
                const int m = bd * 192 + wm * 48 + mt * 16 + g;
#pragma unroll
                for (int nt = 0; nt < 2; ++nt) {
                    const int p0 = 8 * t + wn * 2 + nt;
                    qkv[QIDX(m, p0)]         = acc[bd][mt][nt][0];
                    qkv[QIDX(m, p0 + 4)]     = acc[bd][mt][nt][1];
                    qkv[QIDX(m + 8, p0)]     = acc[bd][mt][nt][2];
                    qkv[QIDX(m + 8, p0 + 4)] = acc[bd][mt][nt][3];
                }
            }
        __syncthreads();

        attn_lh(qkv, subt, warp, lane);    // all heads, both bands
        __syncthreads();
    }

    // ======== MID GEMM: w_m @ sub_t[:, 64..192) ========
    {
        float acc[3][4][4];
#pragma unroll
        for (int mt = 0; mt < 3; ++mt)
#pragma unroll
            for (int nt = 0; nt < 4; ++nt)
                acc[mt][nt][0] = acc[mt][nt][1] = acc[mt][nt][2] = acc[mt][nt][3] = 0.f;

#pragma unroll
        for (int kk = 0; kk < 8; ++kk) {
            uint4 af[3];
#pragma unroll
            for (int mt = 0; mt < 3; ++mt)
                af[mt] = g_wfrag_m[((warp * 3 + mt) * 8 + kk) * 32 + lane];

            unsigned bf[4][2];
            const int kcol = 64 + kk * 16 + 2 * t;
#pragma unroll
            for (int nt = 0; nt < 4; ++nt) {
                const __half* sr = &subt[(nt * 8 + g) * STH + kcol];
                bf[nt][0] = *(const unsigned*)&sr[0];
                bf[nt][1] = *(const unsigned*)&sr[8];
            }
#pragma unroll
            for (int mt = 0; mt < 3; ++mt)
#pragma unroll
                for (int nt = 0; nt < 4; ++nt)
                    mma16(acc[mt][nt], af[mt], bf[nt][0], bf[nt][1]);
        }
#pragma unroll
        for (int mt = 0; mt < 3; ++mt) {
            const int m = warp * 48 + mt * 16 + g;
#pragma unroll
            for (int nt = 0; nt < 4; ++nt) {
                const int p0 = 8 * t + nt;
                qkv[QIDX(m, p0)]         = acc[mt][nt][0];
                qkv[QIDX(m, p0 + 4)]     = acc[mt][nt][1];
                qkv[QIDX(m + 8, p0)]     = acc[mt][nt][2];
                qkv[QIDX(m + 8, p0 + 4)] = acc[mt][nt][3];
            }
        }
        __syncthreads();

        attn_mid(qkv, subt, warp, lane);   // all heads
        __syncthreads();
    }

    // -------- phase 4: IDWT from sub_t (fp16) -> y (float4 stores) ----------
    {
        const int jq = tid & 7;
        const int ch = (tid >> 3) * 2;
        float* ycA = y + (size_t)(b * 64 + ch) * 65536;
        float* ycB = ycA + 65536;
        const int col = xcol0 + 4 * jq;
#pragma unroll
        for (int dy = 0; dy < 2; ++dy) {
            float topA[4], botA[4], topB[4], botB[4];
#pragma unroll
            for (int dx = 0; dx < 2; ++dx) {
                const int row = (2 * dy + dx) * 8 + jq;
                const __half* sr = &subt[row * STH + ch];
                const float2 ll = __half22float2(*(const __half2*)&sr[0]);
                const float2 lh = __half22float2(*(const __half2*)&sr[64]);
                const float2 hl = __half22float2(*(const __half2*)&sr[128]);
                const float2 hh = __half22float2(*(const __half2*)&sr[192]);
                topA[2 * dx]     = (ll.x - lh.x - hl.x + hh.x) * 0.5f;
                topA[2 * dx + 1] = (ll.x - lh.x + hl.x - hh.x) * 0.5f;
                botA[2 * dx]     = (ll.x + lh.x - hl.x - hh.x) * 0.5f;
                botA[2 * dx + 1] = (ll.x + lh.x + hl.x + hh.x) * 0.5f;
                topB[2 * dx]     = (ll.y - lh.y - hl.y + hh.y) * 0.5f;
                topB[2 * dx + 1] = (ll.y - lh.y + hl.y - hh.y) * 0.5f;
                botB[2 * dx]     = (ll.y + lh.y - hl.y - hh.y) * 0.5f;
                botB[2 * dx + 1] = (ll.y + lh.y + hl.y + hh.y) * 0.5f;
            }
            const int r0 = xrow0 + 2 * dy;
            *(float4*)(ycA + r0 * 256 + col)       = make_float4(topA[0], topA[1], topA[2], topA[3]);
            *(float4*)(ycA + (r0 + 1) * 256 + col) = make_float4(botA[0], botA[1], botA[2], botA[3]);
            *(float4*)(ycB + r0 * 256 + col)       = make_float4(topB[0], topB[1], topB[2], topB[3]);
            *(float4*)(ycB + (r0 + 1) * 256 + col) = make_float4(botB[0], botB[1], botB[2], botB[3]);
        }
    }
}

// ---------------------------------------------------------------------------
extern "C" void kernel_launch(void* const* d_in, const int* in_sizes, int n_in,
                              void* d_out, int out_size)
{
    (void)in_sizes; (void)n_in; (void)out_size;
    const float* x    = (const float*)d_in[0];
    const float* w_lh = (const float*)d_in[1];
    const float* w_m  = (const float*)d_in[2];
    float* y = (float*)d_out;

    cudaFuncSetAttribute(wavelet_attn_kernel,
                         cudaFuncAttributeMaxDynamicSharedMemorySize, SMEM_BYTES);

    prep_weights<<<30, 256>>>(w_lh, w_m);

    dim3 grid(8, 64, 8);   // wblk, h, b -> 4096 CTAs
    wavelet_attn_kernel<<<grid, NTH, SMEM_BYTES>>>(x, y);
}

// round 11
// speedup vs baseline: 1.0036x; 1.0036x over previous
#include <cuda_runtime.h>
#include <cuda_fp16.h>
#include <math.h>

// ---------------------------------------------------------------------------
// Fused Haar-DWT -> conv1x1 QKV (fp16 mma.m16n8k16, fp32 accum) -> 2x2-window
// channel-attention (fp32, online softmax) -> Haar-IDWT.
// x (8,64,256,256) f32; w_qkv_lh (192,64); w_qkv_m (384,128).
//
// R11 (= R10 resubmit; R10 hit container infra failure, never ran):
// R9 lane-remapped attention (k/v wavefronts carry 4-8 distinct rows) with
// attention d-loop unroll cut 8 -> 2 so q/o/sm arrays stay in registers
// (R9 spilled ~36 regs/thread to local -> +145MB DRAM, eating the L1 win).
// 72 KB SMEM, 256 threads, 3 CTAs/SM.
// ---------------------------------------------------------------------------

#define NTH  256
#define STH  264            // sub_t row stride (halves); 132 words == 4 mod 32
#define QP   36             // qkv row stride (floats)

#define SUBT_BYTES  (32 * STH * 2)          // 16896
#define QKV_FLOATS  (384 * QP)              // 13824
#define SMEM_BYTES  (SUBT_BYTES + QKV_FLOATS * 4)   // 72192

// qkv swizzle: q-load spread from row>>2, C-store decorrelation from row&3
#define QIDX(row, col) ((row) * QP + \
    (((col) ^ ((((row) >> 2) & 7) << 2)) ^ (((row) & 3) << 3)))

// fragment-ordered fp16 weight images: tile(M16,K16) x 32 lanes x uint4
__device__ uint4 g_wfrag_lh[12 * 4 * 32];
__device__ uint4 g_wfrag_m [24 * 8 * 32];

__device__ __forceinline__ unsigned pack2(float a, float b) {
    __half2 h = __floats2half2_rn(a, b);   // .x (low) = a
    return *(unsigned*)&h;
}
__device__ __forceinline__ float ex2f(float x) {
    float r; asm("ex2.approx.ftz.f32 %0, %1;" : "=f"(r) : "f"(x)); return r;
}
__device__ __forceinline__ float rcpf(float x) {
    float r; asm("rcp.approx.ftz.f32 %0, %1;" : "=f"(r) : "f"(x)); return r;
}

// scale * log2(e)
#define SC2_LH  0.36067376022224085f   // 0.25      * log2(e)
#define SC2_M   0.25505003980080184f   // 0.1767767 * log2(e)

// D += A(16x16,row) * B(16x8,col), fp16 in, fp32 accum
__device__ __forceinline__ void mma16(float* d, const uint4 a, unsigned b0, unsigned b1) {
    asm volatile(
        "mma.sync.aligned.m16n8k16.row.col.f32.f16.f16.f32 "
        "{%0,%1,%2,%3}, {%4,%5,%6,%7}, {%8,%9}, {%0,%1,%2,%3};"
        : "+f"(d[0]), "+f"(d[1]), "+f"(d[2]), "+f"(d[3])
        : "r"(a.x), "r"(a.y), "r"(a.z), "r"(a.w), "r"(b0), "r"(b1));
}

// ---------------------------------------------------------------------------
// prep: fragment-order the weights in fp16.
// ---------------------------------------------------------------------------
__global__ void prep_weights(const float* __restrict__ w_lh,
                             const float* __restrict__ w_m)
{
    const int i = blockIdx.x * blockDim.x + threadIdx.x;
    const int lane = i & 31;
    const int g = lane >> 2, t = lane & 3;
    if (i < 12 * 4 * 32) {
        const int T = i >> 5;
        const int kk = T & 3, mt = T >> 2;
        const int m = mt * 16 + g, k = kk * 16 + 2 * t;
        uint4 v;
        v.x = pack2(w_lh[m * 64 + k],           w_lh[m * 64 + k + 1]);
        v.y = pack2(w_lh[(m + 8) * 64 + k],     w_lh[(m + 8) * 64 + k + 1]);
        v.z = pack2(w_lh[m * 64 + k + 8],       w_lh[m * 64 + k + 9]);
        v.w = pack2(w_lh[(m + 8) * 64 + k + 8], w_lh[(m + 8) * 64 + k + 9]);
        g_wfrag_lh[T * 32 + lane] = v;
    } else {
        const int j = i - 12 * 4 * 32;
        if (j < 24 * 8 * 32) {
            const int T = j >> 5;
            const int kk = T & 7, mt = T >> 3;
            const int m = mt * 16 + g, k = kk * 16 + 2 * t;
            uint4 v;
            v.x = pack2(w_m[m * 128 + k],           w_m[m * 128 + k + 1]);
            v.y = pack2(w_m[(m + 8) * 128 + k],     w_m[(m + 8) * 128 + k + 1]);
            v.z = pack2(w_m[m * 128 + k + 8],       w_m[m * 128 + k + 9]);
            v.w = pack2(w_m[(m + 8) * 128 + k + 8], w_m[(m + 8) * 128 + k + 9]);
            g_wfrag_m[T * 32 + lane] = v;
        }
    }
}

// ---------------------------------------------------------------------------
// low+high attention, all heads+bands in one call.
// lane = (band, head, j): band=lane>>4, hd=(lane>>2)&3, j=lane&3.
// Each lane: 4 q-rows r = j+4i. k/v loads hit 8 distinct rows per warp.
// ---------------------------------------------------------------------------
__device__ __forceinline__ void attn_lh(
    const float* __restrict__ qkv, __half* __restrict__ subt,
    int wi, int lane)
{
    const int c0 = wi * 4;
    const int qb = (lane >> 4) * 192;          // 0 (low) or 192 (high)
    const int hd = (lane >> 2) & 3;
    const int j  = lane & 3;

    float4 q[4];
#pragma unroll
    for (int i = 0; i < 4; ++i)
        q[i] = *(const float4*)&qkv[QIDX(qb + (j + 4 * i) * 4 + hd, c0)];

    float sm[4] = {0.f, 0.f, 0.f, 0.f};
    float o[4][4];
#pragma unroll
    for (int i = 0; i < 4; ++i)
        o[i][0] = o[i][1] = o[i][2] = o[i][3] = 0.f;

#pragma unroll 2
    for (int d = 0; d < 16; ++d) {
        const float4 k4 = *(const float4*)&qkv[QIDX(qb + 64  + d * 4 + hd, c0)];
        const float4 v4 = *(const float4*)&qkv[QIDX(qb + 128 + d * 4 + hd, c0)];
#pragma unroll
        for (int i = 0; i < 4; ++i) {
            const float p = ex2f((q[i].x * k4.x + q[i].y * k4.y +
                                  q[i].z * k4.z + q[i].w * k4.w) * SC2_LH);
            sm[i] += p;
            o[i][0] = fmaf(p, v4.x, o[i][0]);
            o[i][1] = fmaf(p, v4.y, o[i][1]);
            o[i][2] = fmaf(p, v4.z, o[i][2]);
            o[i][3] = fmaf(p, v4.w, o[i][3]);
        }
    }
#pragma unroll
    for (int i = 0; i < 4; ++i) {
        const float inv = rcpf(sm[i]);
        const int ch = qb + (j + 4 * i) * 4 + hd;
#pragma unroll
        for (int pos = 0; pos < 4; ++pos)
            subt[(pos * 8 + wi) * STH + ch] = __float2half_rn(o[i][pos] * inv);
    }
}

// ---------------------------------------------------------------------------
// mid attention, all heads in one call.
// lane = (head, j): hd=lane>>3, j=lane&7. Each lane: 4 q-rows r = j+8i.
// k/v loads hit 4 distinct rows per warp (64B useful per wavefront).
// ---------------------------------------------------------------------------
__device__ __forceinline__ void attn_mid(
    const float* __restrict__ qkv, __half* __restrict__ subt,
    int wi, int lane)
{
    const int c0 = wi * 4;
    const int hd = lane >> 3;
    const int j  = lane & 7;

    float4 q[4];
#pragma unroll
    for (int i = 0; i < 4; ++i)
        q[i] = *(const float4*)&qkv[QIDX((j + 8 * i) * 4 + hd, c0)];

    float sm[4] = {0.f, 0.f, 0.f, 0.f};
    float o[4][4];
#pragma unroll
    for (int i = 0; i < 4; ++i)
        o[i][0] = o[i][1] = o[i][2] = o[i][3] = 0.f;

#pragma unroll 2
    for (int d = 0; d < 32; ++d) {
        const float4 k4 = *(const float4*)&qkv[QIDX(128 + d * 4 + hd, c0)];
        const float4 v4 = *(const float4*)&qkv[QIDX(256 + d * 4 + hd, c0)];
#pragma unroll
        for (int i = 0; i < 4; ++i) {
            const float p = ex2f((q[i].x * k4.x + q[i].y * k4.y +
                                  q[i].z * k4.z + q[i].w * k4.w) * SC2_M);
            sm[i] += p;
            o[i][0] = fmaf(p, v4.x, o[i][0]);
            o[i][1] = fmaf(p, v4.y, o[i][1]);
            o[i][2] = fmaf(p, v4.z, o[i][2]);
            o[i][3] = fmaf(p, v4.w, o[i][3]);
        }
    }
#pragma unroll
    for (int i = 0; i < 4; ++i) {
        const float inv = rcpf(sm[i]);
        const int ch = 64 + (j + 8 * i) * 4 + hd;
#pragma unroll
        for (int pos = 0; pos < 4; ++pos)
            subt[(pos * 8 + wi) * STH + ch] = __float2half_rn(o[i][pos] * inv);
    }
}

// ---------------------------------------------------------------------------
__global__ void __launch_bounds__(NTH, 3)
wavelet_attn_kernel(const float* __restrict__ x,
                    float* __restrict__ y)
{
    extern __shared__ char smem[];
    __half* subt = (__half*)smem;                       // 32 x STH halves
    float*  qkv  = (float*)(smem + SUBT_BYTES);         // 384 x QP floats

    const int tid  = threadIdx.x;
    const int wblk = blockIdx.x;       // 0..7
    const int h    = blockIdx.y;       // 0..63
    const int b    = blockIdx.z;       // 0..7

    const int warp = tid >> 5, lane = tid & 31;
    const int g = lane >> 2, t = lane & 3;

    const int xrow0 = 4 * h;
    const int xcol0 = 32 * wblk;
    const float* xb = x + (size_t)(b * 64) * 65536;

    // -------- phase 0: load x (float4), DWT -> sub_t (fp16, permuted rows) --
    {
        const int jq = tid & 7;
        const int ch = (tid >> 3) * 2;
        const float* xcA = xb + (size_t)ch * 65536;
        const float* xcB = xcA + 65536;
        const int col = xcol0 + 4 * jq;
#pragma unroll
        for (int dy = 0; dy < 2; ++dy) {
            const int r0 = xrow0 + 2 * dy;
            const float4 tA = *(const float4*)(xcA + r0 * 256 + col);
            const float4 uA = *(const float4*)(xcA + (r0 + 1) * 256 + col);
            const float4 tB = *(const float4*)(xcB + r0 * 256 + col);
            const float4 uB = *(const float4*)(xcB + (r0 + 1) * 256 + col);
#pragma unroll
            for (int dx = 0; dx < 2; ++dx) {
                const float aA = dx ? tA.z : tA.x, bA = dx ? tA.w : tA.y;
                const float cA = dx ? uA.z : uA.x, dA = dx ? uA.w : uA.y;
                const float aB = dx ? tB.z : tB.x, bB = dx ? tB.w : tB.y;
                const float cB = dx ? uB.z : uB.x, dB = dx ? uB.w : uB.y;
                const int row = (2 * dy + dx) * 8 + jq;
                __half* sr = &subt[row * STH + ch];
                *(unsigned*)&sr[0]   = pack2(( aA + bA + cA + dA) * 0.5f,
                                             ( aB + bB + cB + dB) * 0.5f);  // ll
                *(unsigned*)&sr[64]  = pack2((-aA - bA + cA + dA) * 0.5f,
                                             (-aB - bB + cB + dB) * 0.5f);  // lh
                *(unsigned*)&sr[128] = pack2((-aA + bA - cA + dA) * 0.5f,
                                             (-aB + bB - cB + dB) * 0.5f);  // hl
                *(unsigned*)&sr[192] = pack2(( aA - bA - cA + dA) * 0.5f,
                                             ( aB - bB - cB + dB) * 0.5f);  // hh
            }
        }
    }
    __syncthreads();

    // ======== fused LOW+HIGH GEMM (one pass over w_lh fragments) ========
    {
        const int wm = warp >> 1, wn = warp & 1;   // 4x2 warp grid
        float acc[2][3][2][4];
#pragma unroll
        for (int bd = 0; bd < 2; ++bd)
#pragma unroll
            for (int mt = 0; mt < 3; ++mt)
#pragma unroll
                for (int nt = 0; nt < 2; ++nt)
                    acc[bd][mt][nt][0] = acc[bd][mt][nt][1] =
                    acc[bd][mt][nt][2] = acc[bd][mt][nt][3] = 0.f;

#pragma unroll
        for (int kk = 0; kk < 4; ++kk) {
            uint4 af[3];
#pragma unroll
            for (int mt = 0; mt < 3; ++mt)
                af[mt] = g_wfrag_lh[((wm * 3 + mt) * 4 + kk) * 32 + lane];

            unsigned bl[2][2], bh[2][2];
            const int kcol = kk * 16 + 2 * t;
#pragma unroll
            for (int nt = 0; nt < 2; ++nt) {
                const int row = (wn * 2 + nt) * 8 + g;
                const __half* sr = &subt[row * STH + kcol];
                bl[nt][0] = *(const unsigned*)&sr[0];
                bl[nt][1] = *(const unsigned*)&sr[8];
                bh[nt][0] = *(const unsigned*)&sr[192];
                bh[nt][1] = *(const unsigned*)&sr[200];
            }
#pragma unroll
            for (int mt = 0; mt < 3; ++mt)
#pragma unroll
                for (int nt = 0; nt < 2; ++nt) {
                    mma16(acc[0][mt][nt], af[mt], bl[nt][0], bl[nt][1]);
                    mma16(acc[1][mt][nt], af[mt], bh[nt][0], bh[nt][1]);
                }
        }
        // C store (un-permute rows -> pos cols): n=2t -> pos 8t+2wn+nt; n+1 -> +4
#pragma unroll
        for (int bd = 0; bd < 2; ++bd)
#pragma unroll
            for (int mt = 0; mt < 3; ++mt) {
                const int m = bd * 192 + wm * 48 + mt * 16 + g;
#pragma unroll
                for (int nt = 0; nt < 2; ++nt) {
                    const int p0 = 8 * t + wn * 2 + nt;
                    qkv[QIDX(m, p0)]         = acc[bd][mt][nt][0];
                    qkv[QIDX(m, p0 + 4)]     = acc[bd][mt][nt][1];
                    qkv[QIDX(m + 8, p0)]     = acc[bd][mt][nt][2];
                    qkv[QIDX(m + 8, p0 + 4)] = acc[bd][mt][nt][3];
                }
            }
        __syncthreads();

        attn_lh(qkv, subt, warp, lane);    // all heads, both bands
        __syncthreads();
    }

    // ======== MID GEMM: w_m @ sub_t[:, 64..192) ========
    {
        float acc[3][4][4];
#pragma unroll
        for (int mt = 0; mt < 3; ++mt)
#pragma unroll
            for (int nt = 0; nt < 4; ++nt)
                acc[mt][nt][0] = acc[mt][nt][1] = acc[mt][nt][2] = acc[mt][nt][3] = 0.f;

#pragma unroll
        for (int kk = 0; kk < 8; ++kk) {
            uint4 af[3];
#pragma unroll
            for (int mt = 0; mt < 3; ++mt)
                af[mt] = g_wfrag_m[((warp * 3 + mt) * 8 + kk) * 32 + lane];

            unsigned bf[4][2];
            const int kcol = 64 + kk * 16 + 2 * t;
#pragma unroll
            for (int nt = 0; nt < 4; ++nt) {
                const __half* sr = &subt[(nt * 8 + g) * STH + kcol];
                bf[nt][0] = *(const unsigned*)&sr[0];
                bf[nt][1] = *(const unsigned*)&sr[8];
            }
#pragma unroll
            for (int mt = 0; mt < 3; ++mt)
#pragma unroll
                for (int nt = 0; nt < 4; ++nt)
                    mma16(acc[mt][nt], af[mt], bf[nt][0], bf[nt][1]);
        }
#pragma unroll
        for (int mt = 0; mt < 3; ++mt) {
            const int m = warp * 48 + mt * 16 + g;
#pragma unroll
            for (int nt = 0; nt < 4; ++nt) {
                const int p0 = 8 * t + nt;
                qkv[QIDX(m, p0)]         = acc[mt][nt][0];
                qkv[QIDX(m, p0 + 4)]     = acc[mt][nt][1];
                qkv[QIDX(m + 8, p0)]     = acc[mt][nt][2];
                qkv[QIDX(m + 8, p0 + 4)] = acc[mt][nt][3];
            }
        }
        __syncthreads();

        attn_mid(qkv, subt, warp, lane);   // all heads
        __syncthreads();
    }

    // -------- phase 4: IDWT from sub_t (fp16) -> y (float4 stores) ----------
    {
        const int jq = tid & 7;
        const int ch = (tid >> 3) * 2;
        float* ycA = y + (size_t)(b * 64 + ch) * 65536;
        float* ycB = ycA + 65536;
        const int col = xcol0 + 4 * jq;
#pragma unroll
        for (int dy = 0; dy < 2; ++dy) {
            float topA[4], botA[4], topB[4], botB[4];
#pragma unroll
            for (int dx = 0; dx < 2; ++dx) {
                const int row = (2 * dy + dx) * 8 + jq;
                const __half* sr = &subt[row * STH + ch];
                const float2 ll = __half22float2(*(const __half2*)&sr[0]);
                const float2 lh = __half22float2(*(const __half2*)&sr[64]);
                const float2 hl = __half22float2(*(const __half2*)&sr[128]);
                const float2 hh = __half22float2(*(const __half2*)&sr[192]);
                topA[2 * dx]     = (ll.x - lh.x - hl.x + hh.x) * 0.5f;
                topA[2 * dx + 1] = (ll.x - lh.x + hl.x - hh.x) * 0.5f;
                botA[2 * dx]     = (ll.x + lh.x - hl.x - hh.x) * 0.5f;
                botA[2 * dx + 1] = (ll.x + lh.x + hl.x + hh.x) * 0.5f;
                topB[2 * dx]     = (ll.y - lh.y - hl.y + hh.y) * 0.5f;
                topB[2 * dx + 1] = (ll.y - lh.y + hl.y - hh.y) * 0.5f;
                botB[2 * dx]     = (ll.y + lh.y - hl.y - hh.y) * 0.5f;
                botB[2 * dx + 1] = (ll.y + lh.y + hl.y + hh.y) * 0.5f;
            }
            const int r0 = xrow0 + 2 * dy;
            *(float4*)(ycA + r0 * 256 + col)       = make_float4(topA[0], topA[1], topA[2], topA[3]);
            *(float4*)(ycA + (r0 + 1) * 256 + col) = make_float4(botA[0], botA[1], botA[2], botA[3]);
            *(float4*)(ycB + r0 * 256 + col)       = make_float4(topB[0], topB[1], topB[2], topB[3]);
            *(float4*)(ycB + (r0 + 1) * 256 + col) = make_float4(botB[0], botB[1], botB[2], botB[3]);
        }
    }
}

// ---------------------------------------------------------------------------
extern "C" void kernel_launch(void* const* d_in, const int* in_sizes, int n_in,
                              void* d_out, int out_size)
{
    (void)in_sizes; (void)n_in; (void)out_size;
    const float* x    = (const float*)d_in[0];
    const float* w_lh = (const float*)d_in[1];
    const float* w_m  = (const float*)d_in[2];
    float* y = (float*)d_out;

    cudaFuncSetAttribute(wavelet_attn_kernel,
                         cudaFuncAttributeMaxDynamicSharedMemorySize, SMEM_BYTES);

    prep_weights<<<30, 256>>>(w_lh, w_m);

    dim3 grid(8, 64, 8);   // wblk, h, b -> 4096 CTAs
    wavelet_attn_kernel<<<grid, NTH, SMEM_BYTES>>>(x, y);
}

// round 12
// speedup vs baseline: 1.0675x; 1.0637x over previous
#include <cuda_runtime.h>
#include <cuda_fp16.h>
#include <math.h>

// ---------------------------------------------------------------------------
// Fused Haar-DWT -> conv1x1 QKV (fp16 mma.m16n8k16, fp32 accum) -> 2x2-window
// channel-attention (fp32, online softmax) -> Haar-IDWT.
// x (8,64,256,256) f32; w_qkv_lh (192,64); w_qkv_m (384,128).
//
// R12: lane-remapped attention (k/v wavefronts carry 4-8 distinct rows) with
// the 4 q-rows processed in TWO PASSES of 2 (pass loop unroll-1) so the
// persistent q/o/sm state is <= ~35 regs -> no local spills (R9/R11 spilled
// ~170MB of local traffic; DRAM 20%). k/v rows read twice, still 2x fewer
// k/v wavefronts than the R8 broadcast scheme.
// 72 KB SMEM, 256 threads, 3 CTAs/SM.
// ---------------------------------------------------------------------------

#define NTH  256
#define STH  264            // sub_t row stride (halves); 132 words == 4 mod 32
#define QP   36             // qkv row stride (floats)

#define SUBT_BYTES  (32 * STH * 2)          // 16896
#define QKV_FLOATS  (384 * QP)              // 13824
#define SMEM_BYTES  (SUBT_BYTES + QKV_FLOATS * 4)   // 72192

// qkv swizzle: q-load spread from row>>2, C-store decorrelation from row&3
#define QIDX(row, col) ((row) * QP + \
    (((col) ^ ((((row) >> 2) & 7) << 2)) ^ (((row) & 3) << 3)))

// fragment-ordered fp16 weight images: tile(M16,K16) x 32 lanes x uint4
__device__ uint4 g_wfrag_lh[12 * 4 * 32];
__device__ uint4 g_wfrag_m [24 * 8 * 32];

__device__ __forceinline__ unsigned pack2(float a, float b) {
    __half2 h = __floats2half2_rn(a, b);   // .x (low) = a
    return *(unsigned*)&h;
}
__device__ __forceinline__ float ex2f(float x) {
    float r; asm("ex2.approx.ftz.f32 %0, %1;" : "=f"(r) : "f"(x)); return r;
}
__device__ __forceinline__ float rcpf(float x) {
    float r; asm("rcp.approx.ftz.f32 %0, %1;" : "=f"(r) : "f"(x)); return r;
}

// scale * log2(e)
#define SC2_LH  0.36067376022224085f   // 0.25      * log2(e)
#define SC2_M   0.25505003980080184f   // 0.1767767 * log2(e)

// D += A(16x16,row) * B(16x8,col), fp16 in, fp32 accum
__device__ __forceinline__ void mma16(float* d, const uint4 a, unsigned b0, unsigned b1) {
    asm volatile(
        "mma.sync.aligned.m16n8k16.row.col.f32.f16.f16.f32 "
        "{%0,%1,%2,%3}, {%4,%5,%6,%7}, {%8,%9}, {%0,%1,%2,%3};"
        : "+f"(d[0]), "+f"(d[1]), "+f"(d[2]), "+f"(d[3])
        : "r"(a.x), "r"(a.y), "r"(a.z), "r"(a.w), "r"(b0), "r"(b1));
}

// ---------------------------------------------------------------------------
// prep: fragment-order the weights in fp16.
// ---------------------------------------------------------------------------
__global__ void prep_weights(const float* __restrict__ w_lh,
                             const float* __restrict__ w_m)
{
    const int i = blockIdx.x * blockDim.x + threadIdx.x;
    const int lane = i & 31;
    const int g = lane >> 2, t = lane & 3;
    if (i < 12 * 4 * 32) {
        const int T = i >> 5;
        const int kk = T & 3, mt = T >> 2;
        const int m = mt * 16 + g, k = kk * 16 + 2 * t;
        uint4 v;
        v.x = pack2(w_lh[m * 64 + k],           w_lh[m * 64 + k + 1]);
        v.y = pack2(w_lh[(m + 8) * 64 + k],     w_lh[(m + 8) * 64 + k + 1]);
        v.z = pack2(w_lh[m * 64 + k + 8],       w_lh[m * 64 + k + 9]);
        v.w = pack2(w_lh[(m + 8) * 64 + k + 8], w_lh[(m + 8) * 64 + k + 9]);
        g_wfrag_lh[T * 32 + lane] = v;
    } else {
        const int j = i - 12 * 4 * 32;
        if (j < 24 * 8 * 32) {
            const int T = j >> 5;
            const int kk = T & 7, mt = T >> 3;
            const int m = mt * 16 + g, k = kk * 16 + 2 * t;
            uint4 v;
            v.x = pack2(w_m[m * 128 + k],           w_m[m * 128 + k + 1]);
            v.y = pack2(w_m[(m + 8) * 128 + k],     w_m[(m + 8) * 128 + k + 1]);
            v.z = pack2(w_m[m * 128 + k + 8],       w_m[m * 128 + k + 9]);
            v.w = pack2(w_m[(m + 8) * 128 + k + 8], w_m[(m + 8) * 128 + k + 9]);
            g_wfrag_m[T * 32 + lane] = v;
        }
    }
}

// ---------------------------------------------------------------------------
// low+high attention, all heads+bands in one call, 2 q-rows per pass.
// lane = (band, head, j): band=lane>>4, hd=(lane>>2)&3, j=lane&3.
// Pass ps handles q-rows r = j + 4*(2*ps+i), i in {0,1}.
// k/v loads hit 8 distinct rows per warp wavefront.
// ---------------------------------------------------------------------------
__device__ __forceinline__ void attn_lh(
    const float* __restrict__ qkv, __half* __restrict__ subt,
    int wi, int lane)
{
    const int c0 = wi * 4;
    const int qb = (lane >> 4) * 192;          // 0 (low) or 192 (high)
    const int hd = (lane >> 2) & 3;
    const int j  = lane & 3;

#pragma unroll 1
    for (int ps = 0; ps < 2; ++ps) {
        float4 q[2];
#pragma unroll
        for (int i = 0; i < 2; ++i)
            q[i] = *(const float4*)&qkv[QIDX(qb + (j + 4 * (2 * ps + i)) * 4 + hd, c0)];

        float sm[2] = {0.f, 0.f};
        float o[2][4];
#pragma unroll
        for (int i = 0; i < 2; ++i)
            o[i][0] = o[i][1] = o[i][2] = o[i][3] = 0.f;

#pragma unroll 2
        for (int d = 0; d < 16; ++d) {
            const float4 k4 = *(const float4*)&qkv[QIDX(qb + 64  + d * 4 + hd, c0)];
            const float4 v4 = *(const float4*)&qkv[QIDX(qb + 128 + d * 4 + hd, c0)];
#pragma unroll
            for (int i = 0; i < 2; ++i) {
                const float p = ex2f((q[i].x * k4.x + q[i].y * k4.y +
                                      q[i].z * k4.z + q[i].w * k4.w) * SC2_LH);
                sm[i] += p;
                o[i][0] = fmaf(p, v4.x, o[i][0]);
                o[i][1] = fmaf(p, v4.y, o[i][1]);
                o[i][2] = fmaf(p, v4.z, o[i][2]);
                o[i][3] = fmaf(p, v4.w, o[i][3]);
            }
        }
#pragma unroll
        for (int i = 0; i < 2; ++i) {
            const float inv = rcpf(sm[i]);
            const int ch = qb + (j + 4 * (2 * ps + i)) * 4 + hd;
#pragma unroll
            for (int pos = 0; pos < 4; ++pos)
                subt[(pos * 8 + wi) * STH + ch] = __float2half_rn(o[i][pos] * inv);
        }
    }
}

// ---------------------------------------------------------------------------
// mid attention, all heads in one call, 2 q-rows per pass.
// lane = (head, j): hd=lane>>3, j=lane&7. Pass ps: q-rows r = j+8*(2*ps+i).
// k/v loads hit 4 distinct rows per warp wavefront (64B useful).
// ---------------------------------------------------------------------------
__device__ __forceinline__ void attn_mid(
    const float* __restrict__ qkv, __half* __restrict__ subt,
    int wi, int lane)
{
    const int c0 = wi * 4;
    const int hd = lane >> 3;
    const int j  = lane & 7;

#pragma unroll 1
    for (int ps = 0; ps < 2; ++ps) {
        float4 q[2];
#pragma unroll
        for (int i = 0; i < 2; ++i)
            q[i] = *(const float4*)&qkv[QIDX((j + 8 * (2 * ps + i)) * 4 + hd, c0)];

        float sm[2] = {0.f, 0.f};
        float o[2][4];
#pragma unroll
        for (int i = 0; i < 2; ++i)
            o[i][0] = o[i][1] = o[i][2] = o[i][3] = 0.f;

#pragma unroll 2
        for (int d = 0; d < 32; ++d) {
            const float4 k4 = *(const float4*)&qkv[QIDX(128 + d * 4 + hd, c0)];
            const float4 v4 = *(const float4*)&qkv[QIDX(256 + d * 4 + hd, c0)];
#pragma unroll
            for (int i = 0; i < 2; ++i) {
                const float p = ex2f((q[i].x * k4.x + q[i].y * k4.y +
                                      q[i].z * k4.z + q[i].w * k4.w) * SC2_M);
                sm[i] += p;
                o[i][0] = fmaf(p, v4.x, o[i][0]);
                o[i][1] = fmaf(p, v4.y, o[i][1]);
                o[i][2] = fmaf(p, v4.z, o[i][2]);
                o[i][3] = fmaf(p, v4.w, o[i][3]);
            }
        }
#pragma unroll
        for (int i = 0; i < 2; ++i) {
            const float inv = rcpf(sm[i]);
            const int ch = 64 + (j + 8 * (2 * ps + i)) * 4 + hd;
#pragma unroll
            for (int pos = 0; pos < 4; ++pos)
                subt[(pos * 8 + wi) * STH + ch] = __float2half_rn(o[i][pos] * inv);
        }
    }
}

// ---------------------------------------------------------------------------
__global__ void __launch_bounds__(NTH, 3)
wavelet_attn_kernel(const float* __restrict__ x,
                    float* __restrict__ y)
{
    extern __shared__ char smem[];
    __half* subt = (__half*)smem;                       // 32 x STH halves
    float*  qkv  = (float*)(smem + SUBT_BYTES);         // 384 x QP floats

    const int tid  = threadIdx.x;
    const int wblk = blockIdx.x;       // 0..7
    const int h    = blockIdx.y;       // 0..63
    const int b    = blockIdx.z;       // 0..7

    const int warp = tid >> 5, lane = tid & 31;
    const int g = lane >> 2, t = lane & 3;

    const int xrow0 = 4 * h;
    const int xcol0 = 32 * wblk;
    const float* xb = x + (size_t)(b * 64) * 65536;

    // -------- phase 0: load x (float4), DWT -> sub_t (fp16, permuted rows) --
    {
        const int jq = tid & 7;
        const int ch = (tid >> 3) * 2;
        const float* xcA = xb + (size_t)ch * 65536;
        const float* xcB = xcA + 65536;
        const int col = xcol0 + 4 * jq;
#pragma unroll
        for (int dy = 0; dy < 2; ++dy) {
            const int r0 = xrow0 + 2 * dy;
            const float4 tA = *(const float4*)(xcA + r0 * 256 + col);
            const float4 uA = *(const float4*)(xcA + (r0 + 1) * 256 + col);
            const float4 tB = *(const float4*)(xcB + r0 * 256 + col);
            const float4 uB = *(const float4*)(xcB + (r0 + 1) * 256 + col);
#pragma unroll
            for (int dx = 0; dx < 2; ++dx) {
                const float aA = dx ? tA.z : tA.x, bA = dx ? tA.w : tA.y;
                const float cA = dx ? uA.z : uA.x, dA = dx ? uA.w : uA.y;
                const float aB = dx ? tB.z : tB.x, bB = dx ? tB.w : tB.y;
                const float cB = dx ? uB.z : uB.x, dB = dx ? uB.w : uB.y;
                const int row = (2 * dy + dx) * 8 + jq;
                __half* sr = &subt[row * STH + ch];
                *(unsigned*)&sr[0]   = pack2(( aA + bA + cA + dA) * 0.5f,
                                             ( aB + bB + cB + dB) * 0.5f);  // ll
                *(unsigned*)&sr[64]  = pack2((-aA - bA + cA + dA) * 0.5f,
                                             (-aB - bB + cB + dB) * 0.5f);  // lh
                *(unsigned*)&sr[128] = pack2((-aA + bA - cA + dA) * 0.5f,
                                             (-aB + bB - cB + dB) * 0.5f);  // hl
                *(unsigned*)&sr[192] = pack2(( aA - bA - cA + dA) * 0.5f,
                                             ( aB - bB - cB + dB) * 0.5f);  // hh
            }
        }
    }
    __syncthreads();

    // ======== fused LOW+HIGH GEMM (one pass over w_lh fragments) ========
    {
        const int wm = warp >> 1, wn = warp & 1;   // 4x2 warp grid
        float acc[2][3][2][4];
#pragma unroll
        for (int bd = 0; bd < 2; ++bd)
#pragma unroll
            for (int mt = 0; mt < 3; ++mt)
#pragma unroll
                for (int nt = 0; nt < 2; ++nt)
                    acc[bd][mt][nt][0] = acc[bd][mt][nt][1] =
                    acc[bd][mt][nt][2] = acc[bd][mt][nt][3] = 0.f;

#pragma unroll
        for (int kk = 0; kk < 4; ++kk) {
            uint4 af[3];
#pragma unroll
            for (int mt = 0; mt < 3; ++mt)
                af[mt] = g_wfrag_lh[((wm * 3 + mt) * 4 + kk) * 32 + lane];

            unsigned bl[2][2], bh[2][2];
            const int kcol = kk * 16 + 2 * t;
#pragma unroll
            for (int nt = 0; nt < 2; ++nt) {
                const int row = (wn * 2 + nt) * 8 + g;
                const __half* sr = &subt[row * STH + kcol];
                bl[nt][0] = *(const unsigned*)&sr[0];
                bl[nt][1] = *(const unsigned*)&sr[8];
                bh[nt][0] = *(const unsigned*)&sr[192];
                bh[nt][1] = *(const unsigned*)&sr[200];
            }
#pragma unroll
            for (int mt = 0; mt < 3; ++mt)
#pragma unroll
                for (int nt = 0; nt < 2; ++nt) {
                    mma16(acc[0][mt][nt], af[mt], bl[nt][0], bl[nt][1]);
                    mma16(acc[1][mt][nt], af[mt], bh[nt][0], bh[nt][1]);
                }
        }
        // C store (un-permute rows -> pos cols): n=2t -> pos 8t+2wn+nt; n+1 -> +4
#pragma unroll
        for (int bd = 0; bd < 2; ++bd)
#pragma unroll
            for (int mt = 0; mt < 3; ++mt) {
                const int m = bd * 192 + wm * 48 + mt * 16 + g;
#pragma unroll
                for (int nt = 0; nt < 2; ++nt) {
                    const int p0 = 8 * t + wn * 2 + nt;
                    qkv[QIDX(m, p0)]         = acc[bd][mt][nt][0];
                    qkv[QIDX(m, p0 + 4)]     = acc[bd][mt][nt][1];
                    qkv[QIDX(m + 8, p0)]     = acc[bd][mt][nt][2];
                    qkv[QIDX(m + 8, p0 + 4)] = acc[bd][mt][nt][3];
                }
            }
        __syncthreads();

        attn_lh(qkv, subt, warp, lane);    // all heads, both bands
        __syncthreads();
    }

    // ======== MID GEMM: w_m @ sub_t[:, 64..192) ========
    {
        float acc[3][4][4];
#pragma unroll
        for (int mt = 0; mt < 3; ++mt)
#pragma unroll
            for (int nt = 0; nt < 4; ++nt)
                acc[mt][nt][0] = acc[mt][nt][1] = acc[mt][nt][2] = acc[mt][nt][3] = 0.f;

#pragma unroll
        for (int kk = 0; kk < 8; ++kk) {
            uint4 af[3];
#pragma unroll
            for (int mt = 0; mt < 3; ++mt)
                af[mt] = g_wfrag_m[((warp * 3 + mt) * 8 + kk) * 32 + lane];

            unsigned bf[4][2];
            const int kcol = 64 + kk * 16 + 2 * t;
#pragma unroll
            for (int nt = 0; nt < 4; ++nt) {
                const __half* sr = &subt[(nt * 8 + g) * STH + kcol];
                bf[nt][0] = *(const unsigned*)&sr[0];
                bf[nt][1] = *(const unsigned*)&sr[8];
            }
#pragma unroll
            for (int mt = 0; mt < 3; ++mt)
#pragma unroll
                for (int nt = 0; nt < 4; ++nt)
                    mma16(acc[mt][nt], af[mt], bf[nt][0], bf[nt][1]);
        }
#pragma unroll
        for (int mt = 0; mt < 3; ++mt) {
            const int m = warp * 48 + mt * 16 + g;
#pragma unroll
            for (int nt = 0; nt < 4; ++nt) {
                const int p0 = 8 * t + nt;
                qkv[QIDX(m, p0)]         = acc[mt][nt][0];
                qkv[QIDX(m, p0 + 4)]     = acc[mt][nt][1];
                qkv[QIDX(m + 8, p0)]     = acc[mt][nt][2];
                qkv[QIDX(m + 8, p0 + 4)] = acc[mt][nt][3];
            }
        }
        __syncthreads();

        attn_mid(qkv, subt, warp, lane);   // all heads
        __syncthreads();
    }

    // -------- phase 4: IDWT from sub_t (fp16) -> y (float4 stores) ----------
    {
        const int jq = tid & 7;
        const int ch = (tid >> 3) * 2;
        float* ycA = y + (size_t)(b * 64 + ch) * 65536;
        float* ycB = ycA + 65536;
        const int col = xcol0 + 4 * jq;
#pragma unroll
        for (int dy = 0; dy < 2; ++dy) {
            float topA[4], botA[4], topB[4], botB[4];
#pragma unroll
            for (int dx = 0; dx < 2; ++dx) {
                const int row = (2 * dy + dx) * 8 + jq;
                const __half* sr = &subt[row * STH + ch];
                const float2 ll = __half22float2(*(const __half2*)&sr[0]);
                const float2 lh = __half22float2(*(const __half2*)&sr[64]);
                const float2 hl = __half22float2(*(const __half2*)&sr[128]);
                const float2 hh = __half22float2(*(const __half2*)&sr[192]);
                topA[2 * dx]     = (ll.x - lh.x - hl.x + hh.x) * 0.5f;
                topA[2 * dx + 1] = (ll.x - lh.x + hl.x - hh.x) * 0.5f;
                botA[2 * dx]     = (ll.x + lh.x - hl.x - hh.x) * 0.5f;
                botA[2 * dx + 1] = (ll.x + lh.x + hl.x + hh.x) * 0.5f;
                topB[2 * dx]     = (ll.y - lh.y - hl.y + hh.y) * 0.5f;
                topB[2 * dx + 1] = (ll.y - lh.y + hl.y - hh.y) * 0.5f;
                botB[2 * dx]     = (ll.y + lh.y - hl.y - hh.y) * 0.5f;
                botB[2 * dx + 1] = (ll.y + lh.y + hl.y + hh.y) * 0.5f;
            }
            const int r0 = xrow0 + 2 * dy;
            *(float4*)(ycA + r0 * 256 + col)       = make_float4(topA[0], topA[1], topA[2], topA[3]);
            *(float4*)(ycA + (r0 + 1) * 256 + col) = make_float4(botA[0], botA[1], botA[2], botA[3]);
            *(float4*)(ycB + r0 * 256 + col)       = make_float4(topB[0], topB[1], topB[2], topB[3]);
            *(float4*)(ycB + (r0 + 1) * 256 + col) = make_float4(botB[0], botB[1], botB[2], botB[3]);
        }
    }
}

// ---------------------------------------------------------------------------
extern "C" void kernel_launch(void* const* d_in, const int* in_sizes, int n_in,
                              void* d_out, int out_size)
{
    (void)in_sizes; (void)n_in; (void)out_size;
    const float* x    = (const float*)d_in[0];
    const float* w_lh = (const float*)d_in[1];
    const float* w_m  = (const float*)d_in[2];
    float* y = (float*)d_out;

    cudaFuncSetAttribute(wavelet_attn_kernel,
                         cudaFuncAttributeMaxDynamicSharedMemorySize, SMEM_BYTES);

    prep_weights<<<30, 256>>>(w_lh, w_m);

    dim3 grid(8, 64, 8);   // wblk, h, b -> 4096 CTAs
    wavelet_attn_kernel<<<grid, NTH, SMEM_BYTES>>>(x, y);
}

// round 13
// speedup vs baseline: 1.1767x; 1.1023x over previous
#include <cuda_runtime.h>
#include <cuda_fp16.h>
#include <math.h>

// ---------------------------------------------------------------------------
// Fused Haar-DWT -> conv1x1 QKV (fp16 mma.m16n8k16, fp32 accum) -> 2x2-window
// channel-attention (fp32 math, fp16 qkv storage) -> Haar-IDWT.
// x (8,64,256,256) f32; w_qkv_lh (192,64); w_qkv_m (384,128).
//
// R13: qkv buffer moves to fp16. Attention k/v loads become LDS.64
// (2-phase floor vs LDS.128's 4) -> attention L1 phases halve (they were
// ~75% of all L1 work). GEMM C-stores pack half2 pairs (adjacent pos cols)
// -> store count halves. Attention math stays fp32 via convert-on-load.
// Two-pass attention liveness (R12) retained -> no register spills.
// 44.5 KB SMEM, 256 threads, 3 CTAs/SM.
// ---------------------------------------------------------------------------

#define NTH  256
#define STH  264            // sub_t row stride (halves); 132 words == 4 mod 32
#define QPH  36             // qkv row stride (halves, 72B)

#define SUBT_BYTES  (32 * STH * 2)          // 16896
#define QKV_BYTES   (384 * QPH * 2)         // 27648
#define SMEM_BYTES  (SUBT_BYTES + QKV_BYTES)   // 44544

// fp16 qkv swizzle: xor multiple of 4 halves (8B) -> vector alignment kept;
// constant across the 4 head-rows of a k/v group -> broadcast groups intact.
#define QIDXH(row, pos) ((row) * QPH + ((pos) ^ ((((row) >> 2) & 7) << 2)))

// fragment-ordered fp16 weight images: tile(M16,K16) x 32 lanes x uint4
__device__ uint4 g_wfrag_lh[12 * 4 * 32];
__device__ uint4 g_wfrag_m [24 * 8 * 32];

__device__ __forceinline__ unsigned pack2(float a, float b) {
    __half2 h = __floats2half2_rn(a, b);   // .x (low) = a
    return *(unsigned*)&h;
}
__device__ __forceinline__ float ex2f(float x) {
    float r; asm("ex2.approx.ftz.f32 %0, %1;" : "=f"(r) : "f"(x)); return r;
}
__device__ __forceinline__ float rcpf(float x) {
    float r; asm("rcp.approx.ftz.f32 %0, %1;" : "=f"(r) : "f"(x)); return r;
}

// 8-byte qkv vector load (4 halves at pos..pos+3) -> float4
__device__ __forceinline__ float4 ldq4(const __half* qkv, int row, int pos) {
    const uint2 u = *(const uint2*)&qkv[QIDXH(row, pos)];
    const float2 a = __half22float2(*(const __half2*)&u.x);
    const float2 b = __half22float2(*(const __half2*)&u.y);
    return make_float4(a.x, a.y, b.x, b.y);
}
// packed half2 store at (row, pos) = values (pos, pos+1)
__device__ __forceinline__ void stq2(__half* qkv, int row, int pos, float a, float b) {
    *(unsigned*)&qkv[QIDXH(row, pos)] = pack2(a, b);
}

// scale * log2(e)
#define SC2_LH  0.36067376022224085f   // 0.25      * log2(e)
#define SC2_M   0.25505003980080184f   // 0.1767767 * log2(e)

// D += A(16x16,row) * B(16x8,col), fp16 in, fp32 accum
__device__ __forceinline__ void mma16(float* d, const uint4 a, unsigned b0, unsigned b1) {
    asm volatile(
        "mma.sync.aligned.m16n8k16.row.col.f32.f16.f16.f32 "
        "{%0,%1,%2,%3}, {%4,%5,%6,%7}, {%8,%9}, {%0,%1,%2,%3};"
        : "+f"(d[0]), "+f"(d[1]), "+f"(d[2]), "+f"(d[3])
        : "r"(a.x), "r"(a.y), "r"(a.z), "r"(a.w), "r"(b0), "r"(b1));
}

// ---------------------------------------------------------------------------
// prep: fragment-order the weights in fp16.
// ---------------------------------------------------------------------------
__global__ void prep_weights(const float* __restrict__ w_lh,
                             const float* __restrict__ w_m)
{
    const int i = blockIdx.x * blockDim.x + threadIdx.x;
    const int lane = i & 31;
    const int g = lane >> 2, t = lane & 3;
    if (i < 12 * 4 * 32) {
        const int T = i >> 5;
        const int kk = T & 3, mt = T >> 2;
        const int m = mt * 16 + g, k = kk * 16 + 2 * t;
        uint4 v;
        v.x = pack2(w_lh[m * 64 + k],           w_lh[m * 64 + k + 1]);
        v.y = pack2(w_lh[(m + 8) * 64 + k],     w_lh[(m + 8) * 64 + k + 1]);
        v.z = pack2(w_lh[m * 64 + k + 8],       w_lh[m * 64 + k + 9]);
        v.w = pack2(w_lh[(m + 8) * 64 + k + 8], w_lh[(m + 8) * 64 + k + 9]);
        g_wfrag_lh[T * 32 + lane] = v;
    } else {
        const int j = i - 12 * 4 * 32;
        if (j < 24 * 8 * 32) {
            const int T = j >> 5;
            const int kk = T & 7, mt = T >> 3;
            const int m = mt * 16 + g, k = kk * 16 + 2 * t;
            uint4 v;
            v.x = pack2(w_m[m * 128 + k],           w_m[m * 128 + k + 1]);
            v.y = pack2(w_m[(m + 8) * 128 + k],     w_m[(m + 8) * 128 + k + 1]);
            v.z = pack2(w_m[m * 128 + k + 8],       w_m[m * 128 + k + 9]);
            v.w = pack2(w_m[(m + 8) * 128 + k + 8], w_m[(m + 8) * 128 + k + 9]);
            g_wfrag_m[T * 32 + lane] = v;
        }
    }
}

// ---------------------------------------------------------------------------
// low+high attention, all heads+bands, 2 q-rows per pass (bounded liveness).
// lane = (band, head, j): band=lane>>4, hd=(lane>>2)&3, j=lane&3.
// ---------------------------------------------------------------------------
__device__ __forceinline__ void attn_lh(
    const __half* __restrict__ qkv, __half* __restrict__ subt,
    int wi, int lane)
{
    const int c0 = wi * 4;
    const int qb = (lane >> 4) * 192;          // 0 (low) or 192 (high)
    const int hd = (lane >> 2) & 3;
    const int j  = lane & 3;

#pragma unroll 1
    for (int ps = 0; ps < 2; ++ps) {
        float4 q[2];
#pragma unroll
        for (int i = 0; i < 2; ++i)
            q[i] = ldq4(qkv, qb + (j + 4 * (2 * ps + i)) * 4 + hd, c0);

        float sm[2] = {0.f, 0.f};
        float o[2][4];
#pragma unroll
        for (int i = 0; i < 2; ++i)
            o[i][0] = o[i][1] = o[i][2] = o[i][3] = 0.f;

#pragma unroll 2
        for (int d = 0; d < 16; ++d) {
            const float4 k4 = ldq4(qkv, qb + 64  + d * 4 + hd, c0);
            const float4 v4 = ldq4(qkv, qb + 128 + d * 4 + hd, c0);
#pragma unroll
            for (int i = 0; i < 2; ++i) {
                const float p = ex2f((q[i].x * k4.x + q[i].y * k4.y +
                                      q[i].z * k4.z + q[i].w * k4.w) * SC2_LH);
                sm[i] += p;
                o[i][0] = fmaf(p, v4.x, o[i][0]);
                o[i][1] = fmaf(p, v4.y, o[i][1]);
                o[i][2] = fmaf(p, v4.z, o[i][2]);
                o[i][3] = fmaf(p, v4.w, o[i][3]);
            }
        }
#pragma unroll
        for (int i = 0; i < 2; ++i) {
            const float inv = rcpf(sm[i]);
            const int ch = qb + (j + 4 * (2 * ps + i)) * 4 + hd;
#pragma unroll
            for (int pos = 0; pos < 4; ++pos)
                subt[(pos * 8 + wi) * STH + ch] = __float2half_rn(o[i][pos] * inv);
        }
    }
}

// ---------------------------------------------------------------------------
// mid attention, all heads, 2 q-rows per pass.
// lane = (head, j): hd=lane>>3, j=lane&7.
// ---------------------------------------------------------------------------
__device__ __forceinline__ void attn_mid(
    const __half* __restrict__ qkv, __half* __restrict__ subt,
    int wi, int lane)
{
    const int c0 = wi * 4;
    const int hd = lane >> 3;
    const int j  = lane & 7;

#pragma unroll 1
    for (int ps = 0; ps < 2; ++ps) {
        float4 q[2];
#pragma unroll
        for (int i = 0; i < 2; ++i)
            q[i] = ldq4(qkv, (j + 8 * (2 * ps + i)) * 4 + hd, c0);

        float sm[2] = {0.f, 0.f};
        float o[2][4];
#pragma unroll
        for (int i = 0; i < 2; ++i)
            o[i][0] = o[i][1] = o[i][2] = o[i][3] = 0.f;

#pragma unroll 2
        for (int d = 0; d < 32; ++d) {
            const float4 k4 = ldq4(qkv, 128 + d * 4 + hd, c0);
            const float4 v4 = ldq4(qkv, 256 + d * 4 + hd, c0);
#pragma unroll
            for (int i = 0; i < 2; ++i) {
                const float p = ex2f((q[i].x * k4.x + q[i].y * k4.y +
                                      q[i].z * k4.z + q[i].w * k4.w) * SC2_M);
                sm[i] += p;
                o[i][0] = fmaf(p, v4.x, o[i][0]);
                o[i][1] = fmaf(p, v4.y, o[i][1]);
                o[i][2] = fmaf(p, v4.z, o[i][2]);
                o[i][3] = fmaf(p, v4.w, o[i][3]);
            }
        }
#pragma unroll
        for (int i = 0; i < 2; ++i) {
            const float inv = rcpf(sm[i]);
            const int ch = 64 + (j + 8 * (2 * ps + i)) * 4 + hd;
#pragma unroll
            for (int pos = 0; pos < 4; ++pos)
                subt[(pos * 8 + wi) * STH + ch] = __float2half_rn(o[i][pos] * inv);
        }
    }
}

// ---------------------------------------------------------------------------
__global__ void __launch_bounds__(NTH, 3)
wavelet_attn_kernel(const float* __restrict__ x,
                    float* __restrict__ y)
{
    extern __shared__ char smem[];
    __half* subt = (__half*)smem;                       // 32 x STH halves
    __half* qkv  = (__half*)(smem + SUBT_BYTES);        // 384 x QPH halves

    const int tid  = threadIdx.x;
    const int wblk = blockIdx.x;       // 0..7
    const int h    = blockIdx.y;       // 0..63
    const int b    = blockIdx.z;       // 0..7

    const int warp = tid >> 5, lane = tid & 31;
    const int g = lane >> 2, t = lane & 3;

    const int xrow0 = 4 * h;
    const int xcol0 = 32 * wblk;
    const float* xb = x + (size_t)(b * 64) * 65536;

    // -------- phase 0: load x (float4), DWT -> sub_t (fp16, permuted rows) --
    {
        const int jq = tid & 7;
        const int ch = (tid >> 3) * 2;
        const float* xcA = xb + (size_t)ch * 65536;
        const float* xcB = xcA + 65536;
        const int col = xcol0 + 4 * jq;
#pragma unroll
        for (int dy = 0; dy < 2; ++dy) {
            const int r0 = xrow0 + 2 * dy;
            const float4 tA = *(const float4*)(xcA + r0 * 256 + col);
            const float4 uA = *(const float4*)(xcA + (r0 + 1) * 256 + col);
            const float4 tB = *(const float4*)(xcB + r0 * 256 + col);
            const float4 uB = *(const float4*)(xcB + (r0 + 1) * 256 + col);
#pragma unroll
            for (int dx = 0; dx < 2; ++dx) {
                const float aA = dx ? tA.z : tA.x, bA = dx ? tA.w : tA.y;
                const float cA = dx ? uA.z : uA.x, dA = dx ? uA.w : uA.y;
                const float aB = dx ? tB.z : tB.x, bB = dx ? tB.w : tB.y;
                const float cB = dx ? uB.z : uB.x, dB = dx ? uB.w : uB.y;
                const int row = (2 * dy + dx) * 8 + jq;
                __half* sr = &subt[row * STH + ch];
                *(unsigned*)&sr[0]   = pack2(( aA + bA + cA + dA) * 0.5f,
                                             ( aB + bB + cB + dB) * 0.5f);  // ll
                *(unsigned*)&sr[64]  = pack2((-aA - bA + cA + dA) * 0.5f,
                                             (-aB - bB + cB + dB) * 0.5f);  // lh
                *(unsigned*)&sr[128] = pack2((-aA + bA - cA + dA) * 0.5f,
                                             (-aB + bB - cB + dB) * 0.5f);  // hl
                *(unsigned*)&sr[192] = pack2(( aA - bA - cA + dA) * 0.5f,
                                             ( aB - bB - cB + dB) * 0.5f);  // hh
            }
        }
    }
    __syncthreads();

    // ======== fused LOW+HIGH GEMM (one pass over w_lh fragments) ========
    {
        const int wm = warp >> 1, wn = warp & 1;   // 4x2 warp grid
        float acc[2][3][2][4];
#pragma unroll
        for (int bd = 0; bd < 2; ++bd)
#pragma unroll
            for (int mt = 0; mt < 3; ++mt)
#pragma unroll
                for (int nt = 0; nt < 2; ++nt)
                    acc[bd][mt][nt][0] = acc[bd][mt][nt][1] =
                    acc[bd][mt][nt][2] = acc[bd][mt][nt][3] = 0.f;

#pragma unroll
        for (int kk = 0; kk < 4; ++kk) {
            uint4 af[3];
#pragma unroll
            for (int mt = 0; mt < 3; ++mt)
                af[mt] = g_wfrag_lh[((wm * 3 + mt) * 4 + kk) * 32 + lane];

            unsigned bl[2][2], bh[2][2];
            const int kcol = kk * 16 + 2 * t;
#pragma unroll
            for (int nt = 0; nt < 2; ++nt) {
                const int row = (wn * 2 + nt) * 8 + g;
                const __half* sr = &subt[row * STH + kcol];
                bl[nt][0] = *(const unsigned*)&sr[0];
                bl[nt][1] = *(const unsigned*)&sr[8];
                bh[nt][0] = *(const unsigned*)&sr[192];
                bh[nt][1] = *(const unsigned*)&sr[200];
            }
#pragma unroll
            for (int mt = 0; mt < 3; ++mt)
#pragma unroll
                for (int nt = 0; nt < 2; ++nt) {
                    mma16(acc[0][mt][nt], af[mt], bl[nt][0], bl[nt][1]);
                    mma16(acc[1][mt][nt], af[mt], bh[nt][0], bh[nt][1]);
                }
        }
        // C store (packed half2 across nt): pos pairs (8t+2wn, +1) and (+4,+5)
#pragma unroll
        for (int bd = 0; bd < 2; ++bd)
#pragma unroll
            for (int mt = 0; mt < 3; ++mt) {
                const int m  = bd * 192 + wm * 48 + mt * 16 + g;
                const int p0 = 8 * t + wn * 2;
                stq2(qkv, m,     p0,     acc[bd][mt][0][0], acc[bd][mt][1][0]);
                stq2(qkv, m,     p0 + 4, acc[bd][mt][0][1], acc[bd][mt][1][1]);
                stq2(qkv, m + 8, p0,     acc[bd][mt][0][2], acc[bd][mt][1][2]);
                stq2(qkv, m + 8, p0 + 4, acc[bd][mt][0][3], acc[bd][mt][1][3]);
            }
        __syncthreads();

        attn_lh(qkv, subt, warp, lane);    // all heads, both bands
        __syncthreads();
    }

    // ======== MID GEMM: w_m @ sub_t[:, 64..192) ========
    {
        float acc[3][4][4];
#pragma unroll
        for (int mt = 0; mt < 3; ++mt)
#pragma unroll
            for (int nt = 0; nt < 4; ++nt)
                acc[mt][nt][0] = acc[mt][nt][1] = acc[mt][nt][2] = acc[mt][nt][3] = 0.f;

#pragma unroll
        for (int kk = 0; kk < 8; ++kk) {
            uint4 af[3];
#pragma unroll
            for (int mt = 0; mt < 3; ++mt)
                af[mt] = g_wfrag_m[((warp * 3 + mt) * 8 + kk) * 32 + lane];

            unsigned bf[4][2];
            const int kcol = 64 + kk * 16 + 2 * t;
#pragma unroll
            for (int nt = 0; nt < 4; ++nt) {
                const __half* sr = &subt[(nt * 8 + g) * STH + kcol];
                bf[nt][0] = *(const unsigned*)&sr[0];
                bf[nt][1] = *(const unsigned*)&sr[8];
            }
#pragma unroll
            for (int mt = 0; mt < 3; ++mt)
#pragma unroll
                for (int nt = 0; nt < 4; ++nt)
                    mma16(acc[mt][nt], af[mt], bf[nt][0], bf[nt][1]);
        }
        // C store (packed half2): pos blocks 8t..8t+3 (c0/c1) and 8t+4..8t+7
#pragma unroll
        for (int mt = 0; mt < 3; ++mt) {
            const int m  = warp * 48 + mt * 16 + g;
            const int p0 = 8 * t;
            stq2(qkv, m,     p0,     acc[mt][0][0], acc[mt][1][0]);
            stq2(qkv, m,     p0 + 2, acc[mt][2][0], acc[mt][3][0]);
            stq2(qkv, m,     p0 + 4, acc[mt][0][1], acc[mt][1][1]);
            stq2(qkv, m,     p0 + 6, acc[mt][2][1], acc[mt][3][1]);
            stq2(qkv, m + 8, p0,     acc[mt][0][2], acc[mt][1][2]);
            stq2(qkv, m + 8, p0 + 2, acc[mt][2][2], acc[mt][3][2]);
            stq2(qkv, m + 8, p0 + 4, acc[mt][0][3], acc[mt][1][3]);
            stq2(qkv, m + 8, p0 + 6, acc[mt][2][3], acc[mt][3][3]);
        }
        __syncthreads();

        attn_mid(qkv, subt, warp, lane);   // all heads
        __syncthreads();
    }

    // -------- phase 4: IDWT from sub_t (fp16) -> y (float4 stores) ----------
    {
        const int jq = tid & 7;
        const int ch = (tid >> 3) * 2;
        float* ycA = y + (size_t)(b * 64 + ch) * 65536;
        float* ycB = ycA + 65536;
        const int col = xcol0 + 4 * jq;
#pragma unroll
        for (int dy = 0; dy < 2; ++dy) {
            float topA[4], botA[4], topB[4], botB[4];
#pragma unroll
            for (int dx = 0; dx < 2; ++dx) {
                const int row = (2 * dy + dx) * 8 + jq;
                const __half* sr = &subt[row * STH + ch];
                const float2 ll = __half22float2(*(const __half2*)&sr[0]);
                const float2 lh = __half22float2(*(const __half2*)&sr[64]);
                const float2 hl = __half22float2(*(const __half2*)&sr[128]);
                const float2 hh = __half22float2(*(const __half2*)&sr[192]);
                topA[2 * dx]     = (ll.x - lh.x - hl.x + hh.x) * 0.5f;
                topA[2 * dx + 1] = (ll.x - lh.x + hl.x - hh.x) * 0.5f;
                botA[2 * dx]     = (ll.x + lh.x - hl.x - hh.x) * 0.5f;
                botA[2 * dx + 1] = (ll.x + lh.x + hl.x + hh.x) * 0.5f;
                topB[2 * dx]     = (ll.y - lh.y - hl.y + hh.y) * 0.5f;
                topB[2 * dx + 1] = (ll.y - lh.y + hl.y - hh.y) * 0.5f;
                botB[2 * dx]     = (ll.y + lh.y - hl.y - hh.y) * 0.5f;
                botB[2 * dx + 1] = (ll.y + lh.y + hl.y + hh.y) * 0.5f;
            }
            const int r0 = xrow0 + 2 * dy;
            *(float4*)(ycA + r0 * 256 + col)       = make_float4(topA[0], topA[1], topA[2], topA[3]);
            *(float4*)(ycA + (r0 + 1) * 256 + col) = make_float4(botA[0], botA[1], botA[2], botA[3]);
            *(float4*)(ycB + r0 * 256 + col)       = make_float4(topB[0], topB[1], topB[2], topB[3]);
            *(float4*)(ycB + (r0 + 1) * 256 + col) = make_float4(botB[0], botB[1], botB[2], botB[3]);
        }
    }
}

// ---------------------------------------------------------------------------
extern "C" void kernel_launch(void* const* d_in, const int* in_sizes, int n_in,
                              void* d_out, int out_size)
{
    (void)in_sizes; (void)n_in; (void)out_size;
    const float* x    = (const float*)d_in[0];
    const float* w_lh = (const float*)d_in[1];
    const float* w_m  = (const float*)d_in[2];
    float* y = (float*)d_out;

    cudaFuncSetAttribute(wavelet_attn_kernel,
                         cudaFuncAttributeMaxDynamicSharedMemorySize, SMEM_BYTES);

    prep_weights<<<30, 256>>>(w_lh, w_m);

    dim3 grid(8, 64, 8);   // wblk, h, b -> 4096 CTAs
    wavelet_attn_kernel<<<grid, NTH, SMEM_BYTES>>>(x, y);
}

// round 14
// speedup vs baseline: 1.2597x; 1.0705x over previous
#include <cuda_runtime.h>
#include <cuda_fp16.h>
#include <math.h>

// ---------------------------------------------------------------------------
// Fused Haar-DWT -> conv1x1 QKV (fp16 mma.m16n8k16, fp32 accum) -> 2x2-window
// channel-attention (fp32 math, fp16 qkv storage) -> Haar-IDWT.
// x (8,64,256,256) f32; w_qkv_lh (192,64); w_qkv_m (384,128).
//
// R14: issue-slot diet. (1) qkv swizzle re-derived as ((row>>6)&1)<<2 —
// constant per attention k/v stream -> addressing strength-reduces to
// pointer bumps (loops hand-split at the single bit6 flip); also fixes a
// 2-way bank conflict between lh band0/band1 k/v streams. (2) softmax scale
// folded into the q-rows of the prepped weight images -> p = ex2(dot), no
// per-logit FMUL. Two-pass liveness (R12) + fp16 qkv (R13) retained.
// 44.5 KB SMEM, 256 threads, 3 CTAs/SM.
// ---------------------------------------------------------------------------

#define NTH  256
#define STH  264            // sub_t row stride (halves); 132 words == 4 mod 32
#define QPH  36             // qkv row stride (halves, 72B)

#define SUBT_BYTES  (32 * STH * 2)          // 16896
#define QKV_BYTES   (384 * QPH * 2)         // 27648
#define SMEM_BYTES  (SUBT_BYTES + QKV_BYTES)   // 44544

// fp16 qkv swizzle: xor 0 or 4 halves (8B) by row bit6 -> per-stream constant
// in attention; de-conflicts lh band0 vs band1 k/v (banks shift by 2 words).
#define QSW(row)        ((((row) >> 6) & 1) << 2)
#define QIDXH(row, pos) ((row) * QPH + ((pos) ^ QSW(row)))

// fragment-ordered fp16 weight images: tile(M16,K16) x 32 lanes x uint4
__device__ uint4 g_wfrag_lh[12 * 4 * 32];
__device__ uint4 g_wfrag_m [24 * 8 * 32];

__device__ __forceinline__ unsigned pack2(float a, float b) {
    __half2 h = __floats2half2_rn(a, b);   // .x (low) = a
    return *(unsigned*)&h;
}
__device__ __forceinline__ float ex2f(float x) {
    float r; asm("ex2.approx.ftz.f32 %0, %1;" : "=f"(r) : "f"(x)); return r;
}
__device__ __forceinline__ float rcpf(float x) {
    float r; asm("rcp.approx.ftz.f32 %0, %1;" : "=f"(r) : "f"(x)); return r;
}
// 8-byte fp16 vector -> float4
__device__ __forceinline__ float4 h2f4(uint2 u) {
    const float2 a = __half22float2(*(const __half2*)&u.x);
    const float2 b = __half22float2(*(const __half2*)&u.y);
    return make_float4(a.x, a.y, b.x, b.y);
}
// packed half2 store at logical (row, pos) = values (pos, pos+1)
__device__ __forceinline__ void stq2(__half* qkv, int row, int pos, float a, float b) {
    *(unsigned*)&qkv[QIDXH(row, pos)] = pack2(a, b);
}

// scale * log2(e)  (folded into q-rows of the weight images at prep time)
#define SC2_LH  0.36067376022224085f   // 0.25      * log2(e)
#define SC2_M   0.25505003980080184f   // 0.1767767 * log2(e)

// D += A(16x16,row) * B(16x8,col), fp16 in, fp32 accum
__device__ __forceinline__ void mma16(float* d, const uint4 a, unsigned b0, unsigned b1) {
    asm volatile(
        "mma.sync.aligned.m16n8k16.row.col.f32.f16.f16.f32 "
        "{%0,%1,%2,%3}, {%4,%5,%6,%7}, {%8,%9}, {%0,%1,%2,%3};"
        : "+f"(d[0]), "+f"(d[1]), "+f"(d[2]), "+f"(d[3])
        : "r"(a.x), "r"(a.y), "r"(a.z), "r"(a.w), "r"(b0), "r"(b1));
}

// ---------------------------------------------------------------------------
// prep: fragment-order the weights in fp16; q-rows pre-scaled by scale*log2e.
// (q/k boundary at MM/3 is 16-aligned, so m and m+8 share the same region.)
// ---------------------------------------------------------------------------
__global__ void prep_weights(const float* __restrict__ w_lh,
                             const float* __restrict__ w_m)
{
    const int i = blockIdx.x * blockDim.x + threadIdx.x;
    const int lane = i & 31;
    const int g = lane >> 2, t = lane & 3;
    if (i < 12 * 4 * 32) {
        const int T = i >> 5;
        const int kk = T & 3, mt = T >> 2;
        const int m = mt * 16 + g, k = kk * 16 + 2 * t;
        const float s = (m < 64) ? SC2_LH : 1.0f;
        uint4 v;
        v.x = pack2(s * w_lh[m * 64 + k],           s * w_lh[m * 64 + k + 1]);
        v.y = pack2(s * w_lh[(m + 8) * 64 + k],     s * w_lh[(m + 8) * 64 + k + 1]);
        v.z = pack2(s * w_lh[m * 64 + k + 8],       s * w_lh[m * 64 + k + 9]);
        v.w = pack2(s * w_lh[(m + 8) * 64 + k + 8], s * w_lh[(m + 8) * 64 + k + 9]);
        g_wfrag_lh[T * 32 + lane] = v;
    } else {
        const int j = i - 12 * 4 * 32;
        if (j < 24 * 8 * 32) {
            const int T = j >> 5;
            const int kk = T & 7, mt = T >> 3;
            const int m = mt * 16 + g, k = kk * 16 + 2 * t;
            const float s = (m < 128) ? SC2_M : 1.0f;
            uint4 v;
            v.x = pack2(s * w_m[m * 128 + k],           s * w_m[m * 128 + k + 1]);
            v.y = pack2(s * w_m[(m + 8) * 128 + k],     s * w_m[(m + 8) * 128 + k + 1]);
            v.z = pack2(s * w_m[m * 128 + k + 8],       s * w_m[m * 128 + k + 9]);
            v.w = pack2(s * w_m[(m + 8) * 128 + k + 8], s * w_m[(m + 8) * 128 + k + 9]);
            g_wfrag_m[T * 32 + lane] = v;
        }
    }
}

// ---------------------------------------------------------------------------
// low+high attention. lane = (band, head, j). Per-stream swizzle constants:
//  band0: q rows 0..63   sw=0 | k 64..127  sw=4 | v 128..191 sw=0
//  band1: q rows 192..255 sw=4 | k 256..319 sw=0 | v 320..383 sw=4
// ---------------------------------------------------------------------------
__device__ __forceinline__ void attn_lh(
    const __half* __restrict__ qkv, __half* __restrict__ subt,
    int wi, int lane)
{
    const int c0   = wi * 4;
    const int band = lane >> 4;
    const int qb   = band * 192;
    const int hd   = (lane >> 2) & 3;
    const int j    = lane & 3;
    const int cQ   = band ? (c0 ^ 4) : c0;
    const int cK   = band ? c0 : (c0 ^ 4);
    const int cV   = band ? (c0 ^ 4) : c0;

#pragma unroll 1
    for (int ps = 0; ps < 2; ++ps) {
        float4 q[2];
#pragma unroll
        for (int i = 0; i < 2; ++i) {
            const int row = qb + (j + 4 * (2 * ps + i)) * 4 + hd;
            q[i] = h2f4(*(const uint2*)&qkv[row * QPH + cQ]);
        }
        float sm[2] = {0.f, 0.f};
        float o[2][4];
#pragma unroll
        for (int i = 0; i < 2; ++i)
            o[i][0] = o[i][1] = o[i][2] = o[i][3] = 0.f;

        const __half* pk = &qkv[(qb + 64  + hd) * QPH + cK];
        const __half* pv = &qkv[(qb + 128 + hd) * QPH + cV];
#pragma unroll 2
        for (int d = 0; d < 16; ++d) {
            const float4 k4 = h2f4(*(const uint2*)pk); pk += 4 * QPH;
            const float4 v4 = h2f4(*(const uint2*)pv); pv += 4 * QPH;
#pragma unroll
            for (int i = 0; i < 2; ++i) {
                const float p = ex2f(q[i].x * k4.x + q[i].y * k4.y +
                                     q[i].z * k4.z + q[i].w * k4.w);
                sm[i] += p;
                o[i][0] = fmaf(p, v4.x, o[i][0]);
                o[i][1] = fmaf(p, v4.y, o[i][1]);
                o[i][2] = fmaf(p, v4.z, o[i][2]);
                o[i][3] = fmaf(p, v4.w, o[i][3]);
            }
        }
#pragma unroll
        for (int i = 0; i < 2; ++i) {
            const float inv = rcpf(sm[i]);
            const int ch = qb + (j + 4 * (2 * ps + i)) * 4 + hd;
#pragma unroll
            for (int pos = 0; pos < 4; ++pos)
                subt[(pos * 8 + wi) * STH + ch] = __float2half_rn(o[i][pos] * inv);
        }
    }
}

// ---------------------------------------------------------------------------
// mid attention. lane = (head, j). Stream swizzle: q sw = 0 (ps0) / 4 (ps1);
// k rows 128..255 and v rows 256..383 flip sw 0 -> 4 at d = 16 (hand-split).
// ---------------------------------------------------------------------------
__device__ __forceinline__ void attn_mid(
    const __half* __restrict__ qkv, __half* __restrict__ subt,
    int wi, int lane)
{
    const int c0 = wi * 4;
    const int hd = lane >> 3;
    const int j  = lane & 7;

#pragma unroll 1
    for (int ps = 0; ps < 2; ++ps) {
        const int cQ = ps ? (c0 ^ 4) : c0;
        float4 q[2];
#pragma unroll
        for (int i = 0; i < 2; ++i) {
            const int row = (j + 8 * (2 * ps + i)) * 4 + hd;
            q[i] = h2f4(*(const uint2*)&qkv[row * QPH + cQ]);
        }
        float sm[2] = {0.f, 0.f};
        float o[2][4];
#pragma unroll
        for (int i = 0; i < 2; ++i)
            o[i][0] = o[i][1] = o[i][2] = o[i][3] = 0.f;

#pragma unroll 1
        for (int seg = 0; seg < 2; ++seg) {
            const int cs = seg ? (c0 ^ 4) : c0;
            const __half* pk = &qkv[(128 + 64 * seg + hd) * QPH + cs];
            const __half* pv = &qkv[(256 + 64 * seg + hd) * QPH + cs];
#pragma unroll 2
            for (int dd = 0; dd < 16; ++dd) {
                const float4 k4 = h2f4(*(const uint2*)pk); pk += 4 * QPH;
                const float4 v4 = h2f4(*(const uint2*)pv); pv += 4 * QPH;
#pragma unroll
                for (int i = 0; i < 2; ++i) {
                    const float p = ex2f(q[i].x * k4.x + q[i].y * k4.y +
                                         q[i].z * k4.z + q[i].w * k4.w);
                    sm[i] += p;
                    o[i][0] = fmaf(p, v4.x, o[i][0]);
                    o[i][1] = fmaf(p, v4.y, o[i][1]);
                    o[i][2] = fmaf(p, v4.z, o[i][2]);
                    o[i][3] = fmaf(p, v4.w, o[i][3]);
                }
            }
        }
#pragma unroll
        for (int i = 0; i < 2; ++i) {
            const float inv = rcpf(sm[i]);
            const int ch = 64 + (j + 8 * (2 * ps + i)) * 4 + hd;
#pragma unroll
            for (int pos = 0; pos < 4; ++pos)
                subt[(pos * 8 + wi) * STH + ch] = __float2half_rn(o[i][pos] * inv);
        }
    }
}

// ---------------------------------------------------------------------------
__global__ void __launch_bounds__(NTH, 3)
wavelet_attn_kernel(const float* __restrict__ x,
                    float* __restrict__ y)
{
    extern __shared__ char smem[];
    __half* subt = (__half*)smem;                       // 32 x STH halves
    __half* qkv  = (__half*)(smem + SUBT_BYTES);        // 384 x QPH halves

    const int tid  = threadIdx.x;
    const int wblk = blockIdx.x;       // 0..7
    const int h    = blockIdx.y;       // 0..63
    const int b    = blockIdx.z;       // 0..7

    const int warp = tid >> 5, lane = tid & 31;
    const int g = lane >> 2, t = lane & 3;

    const int xrow0 = 4 * h;
    const int xcol0 = 32 * wblk;
    const float* xb = x + (size_t)(b * 64) * 65536;

    // -------- phase 0: load x (float4), DWT -> sub_t (fp16, permuted rows) --
    {
        const int jq = tid & 7;
        const int ch = (tid >> 3) * 2;
        const float* xcA = xb + (size_t)ch * 65536;
        const float* xcB = xcA + 65536;
        const int col = xcol0 + 4 * jq;
#pragma unroll
        for (int dy = 0; dy < 2; ++dy) {
            const int r0 = xrow0 + 2 * dy;
            const float4 tA = *(const float4*)(xcA + r0 * 256 + col);
            const float4 uA = *(const float4*)(xcA + (r0 + 1) * 256 + col);
            const float4 tB = *(const float4*)(xcB + r0 * 256 + col);
            const float4 uB = *(const float4*)(xcB + (r0 + 1) * 256 + col);
#pragma unroll
            for (int dx = 0; dx < 2; ++dx) {
                const float aA = dx ? tA.z : tA.x, bA = dx ? tA.w : tA.y;
                const float cA = dx ? uA.z : uA.x, dA = dx ? uA.w : uA.y;
                const float aB = dx ? tB.z : tB.x, bB = dx ? tB.w : tB.y;
                const float cB = dx ? uB.z : uB.x, dB = dx ? uB.w : uB.y;
                const int row = (2 * dy + dx) * 8 + jq;
                __half* sr = &subt[row * STH + ch];
                *(unsigned*)&sr[0]   = pack2(( aA + bA + cA + dA) * 0.5f,
                                             ( aB + bB + cB + dB) * 0.5f);  // ll
                *(unsigned*)&sr[64]  = pack2((-aA - bA + cA + dA) * 0.5f,
                                             (-aB - bB + cB + dB) * 0.5f);  // lh
                *(unsigned*)&sr[128] = pack2((-aA + bA - cA + dA) * 0.5f,
                                             (-aB + bB - cB + dB) * 0.5f);  // hl
                *(unsigned*)&sr[192] = pack2(( aA - bA - cA + dA) * 0.5f,
                                             ( aB - bB - cB + dB) * 0.5f);  // hh
            }
        }
    }
    __syncthreads();

    // ======== fused LOW+HIGH GEMM (one pass over w_lh fragments) ========
    {
        const int wm = warp >> 1, wn = warp & 1;   // 4x2 warp grid
        float acc[2][3][2][4];
#pragma unroll
        for (int bd = 0; bd < 2; ++bd)
#pragma unroll
            for (int mt = 0; mt < 3; ++mt)
#pragma unroll
                for (int nt = 0; nt < 2; ++nt)
                    acc[bd][mt][nt][0] = acc[bd][mt][nt][1] =
                    acc[bd][mt][nt][2] = acc[bd][mt][nt][3] = 0.f;

#pragma unroll
        for (int kk = 0; kk < 4; ++kk) {
            uint4 af[3];
#pragma unroll
            for (int mt = 0; mt < 3; ++mt)
                af[mt] = g_wfrag_lh[((wm * 3 + mt) * 4 + kk) * 32 + lane];

            unsigned bl[2][2], bh[2][2];
            const int kcol = kk * 16 + 2 * t;
#pragma unroll
            for (int nt = 0; nt < 2; ++nt) {
                const int row = (wn * 2 + nt) * 8 + g;
                const __half* sr = &subt[row * STH + kcol];
                bl[nt][0] = *(const unsigned*)&sr[0];
                bl[nt][1] = *(const unsigned*)&sr[8];
                bh[nt][0] = *(const unsigned*)&sr[192];
                bh[nt][1] = *(const unsigned*)&sr[200];
            }
#pragma unroll
            for (int mt = 0; mt < 3; ++mt)
#pragma unroll
                for (int nt = 0; nt < 2; ++nt) {
                    mma16(acc[0][mt][nt], af[mt], bl[nt][0], bl[nt][1]);
                    mma16(acc[1][mt][nt], af[mt], bh[nt][0], bh[nt][1]);
                }
        }
        // C store (packed half2 across nt): pos pairs (8t+2wn, +1) and (+4,+5)
#pragma unroll
        for (int bd = 0; bd < 2; ++bd)
#pragma unroll
            for (int mt = 0; mt < 3; ++mt) {
                const int m  = bd * 192 + wm * 48 + mt * 16 + g;
                const int p0 = 8 * t + wn * 2;
                stq2(qkv, m,     p0,     acc[bd][mt][0][0], acc[bd][mt][1][0]);
                stq2(qkv, m,     p0 + 4, acc[bd][mt][0][1], acc[bd][mt][1][1]);
                stq2(qkv, m + 8, p0,     acc[bd][mt][0][2], acc[bd][mt][1][2]);
                stq2(qkv, m + 8, p0 + 4, acc[bd][mt][0][3], acc[bd][mt][1][3]);
            }
        __syncthreads();

        attn_lh(qkv, subt, warp, lane);    // all heads, both bands
        __syncthreads();
    }

    // ======== MID GEMM: w_m @ sub_t[:, 64..192) ========
    {
        float acc[3][4][4];
#pragma unroll
        for (int mt = 0; mt < 3; ++mt)
#pragma unroll
            for (int nt = 0; nt < 4; ++nt)
                acc[mt][nt][0] = acc[mt][nt][1] = acc[mt][nt][2] = acc[mt][nt][3] = 0.f;

#pragma unroll
        for (int kk = 0; kk < 8; ++kk) {
            uint4 af[3];
#pragma unroll
            for (int mt = 0; mt < 3; ++mt)
                af[mt] = g_wfrag_m[((warp * 3 + mt) * 8 + kk) * 32 + lane];

            unsigned bf[4][2];
            const int kcol = 64 + kk * 16 + 2 * t;
#pragma unroll
            for (int nt = 0; nt < 4; ++nt) {
                const __half* sr = &subt[(nt * 8 + g) * STH + kcol];
                bf[nt][0] = *(const unsigned*)&sr[0];
                bf[nt][1] = *(const unsigned*)&sr[8];
            }
#pragma unroll
            for (int mt = 0; mt < 3; ++mt)
#pragma unroll
                for (int nt = 0; nt < 4; ++nt)
                    mma16(acc[mt][nt], af[mt], bf[nt][0], bf[nt][1]);
        }
        // C store (packed half2): pos blocks 8t..8t+3 (c0/c1) and 8t+4..8t+7
#pragma unroll
        for (int mt = 0; mt < 3; ++mt) {
            const int m  = warp * 48 + mt * 16 + g;
            const int p0 = 8 * t;
            stq2(qkv, m,     p0,     acc[mt][0][0], acc[mt][1][0]);
            stq2(qkv, m,     p0 + 2, acc[mt][2][0], acc[mt][3][0]);
            stq2(qkv, m,     p0 + 4, acc[mt][0][1], acc[mt][1][1]);
            stq2(qkv, m,     p0 + 6, acc[mt][2][1], acc[mt][3][1]);
            stq2(qkv, m + 8, p0,     acc[mt][0][2], acc[mt][1][2]);
            stq2(qkv, m + 8, p0 + 2, acc[mt][2][2], acc[mt][3][2]);
            stq2(qkv, m + 8, p0 + 4, acc[mt][0][3], acc[mt][1][3]);
            stq2(qkv, m + 8, p0 + 6, acc[mt][2][3], acc[mt][3][3]);
        }
        __syncthreads();

        attn_mid(qkv, subt, warp, lane);   // all heads
        __syncthreads();
    }

    // -------- phase 4: IDWT from sub_t (fp16) -> y (float4 stores) ----------
    {
        const int jq = tid & 7;
        const int ch = (tid >> 3) * 2;
        float* ycA = y + (size_t)(b * 64 + ch) * 65536;
        float* ycB = ycA + 65536;
        const int col = xcol0 + 4 * jq;
#pragma unroll
        for (int dy = 0; dy < 2; ++dy) {
            float topA[4], botA[4], topB[4], botB[4];
#pragma unroll
            for (int dx = 0; dx < 2; ++dx) {
                const int row = (2 * dy + dx) * 8 + jq;
                const __half* sr = &subt[row * STH + ch];
                const float2 ll = __half22float2(*(const __half2*)&sr[0]);
                const float2 lh = __half22float2(*(const __half2*)&sr[64]);
                const float2 hl = __half22float2(*(const __half2*)&sr[128]);
                const float2 hh = __half22float2(*(const __half2*)&sr[192]);
                topA[2 * dx]     = (ll.x - lh.x - hl.x + hh.x) * 0.5f;
                topA[2 * dx + 1] = (ll.x - lh.x + hl.x - hh.x) * 0.5f;
                botA[2 * dx]     = (ll.x + lh.x - hl.x - hh.x) * 0.5f;
                botA[2 * dx + 1] = (ll.x + lh.x + hl.x + hh.x) * 0.5f;
                topB[2 * dx]     = (ll.y - lh.y - hl.y + hh.y) * 0.5f;
                topB[2 * dx + 1] = (ll.y - lh.y + hl.y - hh.y) * 0.5f;
                botB[2 * dx]     = (ll.y + lh.y - hl.y - hh.y) * 0.5f;
                botB[2 * dx + 1] = (ll.y + lh.y + hl.y + hh.y) * 0.5f;
            }
            const int r0 = xrow0 + 2 * dy;
            *(float4*)(ycA + r0 * 256 + col)       = make_float4(topA[0], topA[1], topA[2], topA[3]);
            *(float4*)(ycA + (r0 + 1) * 256 + col) = make_float4(botA[0], botA[1], botA[2], botA[3]);
            *(float4*)(ycB + r0 * 256 + col)       = make_float4(topB[0], topB[1], topB[2], topB[3]);
            *(float4*)(ycB + (r0 + 1) * 256 + col) = make_float4(botB[0], botB[1], botB[2], botB[3]);
        }
    }
}

// ---------------------------------------------------------------------------
extern "C" void kernel_launch(void* const* d_in, const int* in_sizes, int n_in,
                              void* d_out, int out_size)
{
    (void)in_sizes; (void)n_in; (void)out_size;
    const float* x    = (const float*)d_in[0];
    const float* w_lh = (const float*)d_in[1];
    const float* w_m  = (const float*)d_in[2];
    float* y = (float*)d_out;

    cudaFuncSetAttribute(wavelet_attn_kernel,
                         cudaFuncAttributeMaxDynamicSharedMemorySize, SMEM_BYTES);

    prep_weights<<<30, 256>>>(w_lh, w_m);

    dim3 grid(8, 64, 8);   // wblk, h, b -> 4096 CTAs
    wavelet_attn_kernel<<<grid, NTH, SMEM_BYTES>>>(x, y);
}

// round 15
// speedup vs baseline: 1.2725x; 1.0102x over previous
#include <cuda_runtime.h>
#include <cuda_fp16.h>
#include <math.h>

// ---------------------------------------------------------------------------
// Fused Haar-DWT -> conv1x1 QKV (fp16 mma.m16n8k16, fp32 accum) -> 2x2-window
// channel-attention (fp32 math, fp16 qkv storage) -> Haar-IDWT.
// x (8,64,256,256) f32; w_qkv_lh (192,64); w_qkv_m (384,128).
//
// R15: (1) Haar butterfly both directions; DWT's *0.5 folded into the weight
// images (exact fp16 exponent shift; GEMM numerics bit-identical).
// (2) post-attn_lh barrier deferred past the mid-GEMM mainloop (subt column
// ranges are disjoint; qkv hazard only at the mid C-store). (3) attention
// d-loop unroll 2 -> 4 (persistent state ~18 regs, fits cap 85; DRAM% is
// the spill sentinel). R12 two-pass + R13 fp16 qkv + R14 swizzle retained.
// 44.5 KB SMEM, 256 threads, 3 CTAs/SM.
// ---------------------------------------------------------------------------

#define NTH  256
#define STH  264            // sub_t row stride (halves); 132 words == 4 mod 32
#define QPH  36             // qkv row stride (halves, 72B)

#define SUBT_BYTES  (32 * STH * 2)          // 16896
#define QKV_BYTES   (384 * QPH * 2)         // 27648
#define SMEM_BYTES  (SUBT_BYTES + QKV_BYTES)   // 44544

// fp16 qkv swizzle: xor 0 or 4 halves (8B) by row bit6 -> per-stream constant
#define QSW(row)        ((((row) >> 6) & 1) << 2)
#define QIDXH(row, pos) ((row) * QPH + ((pos) ^ QSW(row)))

// fragment-ordered fp16 weight images: tile(M16,K16) x 32 lanes x uint4
__device__ uint4 g_wfrag_lh[12 * 4 * 32];
__device__ uint4 g_wfrag_m [24 * 8 * 32];

__device__ __forceinline__ unsigned pack2(float a, float b) {
    __half2 h = __floats2half2_rn(a, b);   // .x (low) = a
    return *(unsigned*)&h;
}
__device__ __forceinline__ float ex2f(float x) {
    float r; asm("ex2.approx.ftz.f32 %0, %1;" : "=f"(r) : "f"(x)); return r;
}
__device__ __forceinline__ float rcpf(float x) {
    float r; asm("rcp.approx.ftz.f32 %0, %1;" : "=f"(r) : "f"(x)); return r;
}
// 8-byte fp16 vector -> float4
__device__ __forceinline__ float4 h2f4(uint2 u) {
    const float2 a = __half22float2(*(const __half2*)&u.x);
    const float2 b = __half22float2(*(const __half2*)&u.y);
    return make_float4(a.x, a.y, b.x, b.y);
}
// packed half2 store at logical (row, pos) = values (pos, pos+1)
__device__ __forceinline__ void stq2(__half* qkv, int row, int pos, float a, float b) {
    *(unsigned*)&qkv[QIDXH(row, pos)] = pack2(a, b);
}

// scale * log2(e)
#define SC2_LH  0.36067376022224085f   // 0.25      * log2(e)
#define SC2_M   0.25505003980080184f   // 0.1767767 * log2(e)

// D += A(16x16,row) * B(16x8,col), fp16 in, fp32 accum
__device__ __forceinline__ void mma16(float* d, const uint4 a, unsigned b0, unsigned b1) {
    asm volatile(
        "mma.sync.aligned.m16n8k16.row.col.f32.f16.f16.f32 "
        "{%0,%1,%2,%3}, {%4,%5,%6,%7}, {%8,%9}, {%0,%1,%2,%3};"
        : "+f"(d[0]), "+f"(d[1]), "+f"(d[2]), "+f"(d[3])
        : "r"(a.x), "r"(a.y), "r"(a.z), "r"(a.w), "r"(b0), "r"(b1));
}

// ---------------------------------------------------------------------------
// prep: fragment-order the weights in fp16.
// ALL rows carry the DWT 0.5 (subt stores unhalved butterfly sums);
// q-rows additionally carry scale*log2e for the softmax.
// ---------------------------------------------------------------------------
__global__ void prep_weights(const float* __restrict__ w_lh,
                             const float* __restrict__ w_m)
{
    const int i = blockIdx.x * blockDim.x + threadIdx.x;
    const int lane = i & 31;
    const int g = lane >> 2, t = lane & 3;
    if (i < 12 * 4 * 32) {
        const int T = i >> 5;
        const int kk = T & 3, mt = T >> 2;
        const int m = mt * 16 + g, k = kk * 16 + 2 * t;
        const float s = (m < 64) ? (SC2_LH * 0.5f) : 0.5f;
        uint4 v;
        v.x = pack2(s * w_lh[m * 64 + k],           s * w_lh[m * 64 + k + 1]);
        v.y = pack2(s * w_lh[(m + 8) * 64 + k],     s * w_lh[(m + 8) * 64 + k + 1]);
        v.z = pack2(s * w_lh[m * 64 + k + 8],       s * w_lh[m * 64 + k + 9]);
        v.w = pack2(s * w_lh[(m + 8) * 64 + k + 8], s * w_lh[(m + 8) * 64 + k + 9]);
        g_wfrag_lh[T * 32 + lane] = v;
    } else {
        const int j = i - 12 * 4 * 32;
        if (j < 24 * 8 * 32) {
            const int T = j >> 5;
            const int kk = T & 7, mt = T >> 3;
            const int m = mt * 16 + g, k = kk * 16 + 2 * t;
            const float s = (m < 128) ? (SC2_M * 0.5f) : 0.5f;
            uint4 v;
            v.x = pack2(s * w_m[m * 128 + k],           s * w_m[m * 128 + k + 1]);
            v.y = pack2(s * w_m[(m + 8) * 128 + k],     s * w_m[(m + 8) * 128 + k + 1]);
            v.z = pack2(s * w_m[m * 128 + k + 8],       s * w_m[m * 128 + k + 9]);
            v.w = pack2(s * w_m[(m + 8) * 128 + k + 8], s * w_m[(m + 8) * 128 + k + 9]);
            g_wfrag_m[T * 32 + lane] = v;
        }
    }
}

// ---------------------------------------------------------------------------
// low+high attention. lane = (band, head, j). Per-stream swizzle constants.
// ---------------------------------------------------------------------------
__device__ __forceinline__ void attn_lh(
    const __half* __restrict__ qkv, __half* __restrict__ subt,
    int wi, int lane)
{
    const int c0   = wi * 4;
    const int band = lane >> 4;
    const int qb   = band * 192;
    const int hd   = (lane >> 2) & 3;
    const int j    = lane & 3;
    const int cQ   = band ? (c0 ^ 4) : c0;
    const int cK   = band ? c0 : (c0 ^ 4);
    const int cV   = band ? (c0 ^ 4) : c0;

#pragma unroll 1
    for (int ps = 0; ps < 2; ++ps) {
        float4 q[2];
#pragma unroll
        for (int i = 0; i < 2; ++i) {
            const int row = qb + (j + 4 * (2 * ps + i)) * 4 + hd;
            q[i] = h2f4(*(const uint2*)&qkv[row * QPH + cQ]);
        }
        float sm[2] = {0.f, 0.f};
        float o[2][4];
#pragma unroll
        for (int i = 0; i < 2; ++i)
            o[i][0] = o[i][1] = o[i][2] = o[i][3] = 0.f;

        const __half* pk = &qkv[(qb + 64  + hd) * QPH + cK];
        const __half* pv = &qkv[(qb + 128 + hd) * QPH + cV];
#pragma unroll 4
        for (int d = 0; d < 16; ++d) {
            const float4 k4 = h2f4(*(const uint2*)pk); pk += 4 * QPH;
            const float4 v4 = h2f4(*(const uint2*)pv); pv += 4 * QPH;
#pragma unroll
            for (int i = 0; i < 2; ++i) {
                const float p = ex2f(q[i].x * k4.x + q[i].y * k4.y +
                                     q[i].z * k4.z + q[i].w * k4.w);
                sm[i] += p;
                o[i][0] = fmaf(p, v4.x, o[i][0]);
                o[i][1] = fmaf(p, v4.y, o[i][1]);
                o[i][2] = fmaf(p, v4.z, o[i][2]);
                o[i][3] = fmaf(p, v4.w, o[i][3]);
            }
        }
#pragma unroll
        for (int i = 0; i < 2; ++i) {
            const float inv = rcpf(sm[i]);
            const int ch = qb + (j + 4 * (2 * ps + i)) * 4 + hd;
#pragma unroll
            for (int pos = 0; pos < 4; ++pos)
                subt[(pos * 8 + wi) * STH + ch] = __float2half_rn(o[i][pos] * inv);
        }
    }
}

// ---------------------------------------------------------------------------
// mid attention. lane = (head, j). k/v swizzle flips at d = 16 (hand-split).
// ---------------------------------------------------------------------------
__device__ __forceinline__ void attn_mid(
    const __half* __restrict__ qkv, __half* __restrict__ subt,
    int wi, int lane)
{
    const int c0 = wi * 4;
    const int hd = lane >> 3;
    const int j  = lane & 7;

#pragma unroll 1
    for (int ps = 0; ps < 2; ++ps) {
        const int cQ = ps ? (c0 ^ 4) : c0;
        float4 q[2];
#pragma unroll
        for (int i = 0; i < 2; ++i) {
            const int row = (j + 8 * (2 * ps + i)) * 4 + hd;
            q[i] = h2f4(*(const uint2*)&qkv[row * QPH + cQ]);
        }
        float sm[2] = {0.f, 0.f};
        float o[2][4];
#pragma unroll
        for (int i = 0; i < 2; ++i)
            o[i][0] = o[i][1] = o[i][2] = o[i][3] = 0.f;

#pragma unroll 1
        for (int seg = 0; seg < 2; ++seg) {
            const int cs = seg ? (c0 ^ 4) : c0;
            const __half* pk = &qkv[(128 + 64 * seg + hd) * QPH + cs];
            const __half* pv = &qkv[(256 + 64 * seg + hd) * QPH + cs];
#pragma unroll 4
            for (int dd = 0; dd < 16; ++dd) {
                const float4 k4 = h2f4(*(const uint2*)pk); pk += 4 * QPH;
                const float4 v4 = h2f4(*(const uint2*)pv); pv += 4 * QPH;
#pragma unroll
                for (int i = 0; i < 2; ++i) {
                    const float p = ex2f(q[i].x * k4.x + q[i].y * k4.y +
                                         q[i].z * k4.z + q[i].w * k4.w);
                    sm[i] += p;
                    o[i][0] = fmaf(p, v4.x, o[i][0]);
                    o[i][1] = fmaf(p, v4.y, o[i][1]);
                    o[i][2] = fmaf(p, v4.z, o[i][2]);
                    o[i][3] = fmaf(p, v4.w, o[i][3]);
                }
            }
        }
#pragma unroll
        for (int i = 0; i < 2; ++i) {
            const float inv = rcpf(sm[i]);
            const int ch = 64 + (j + 8 * (2 * ps + i)) * 4 + hd;
#pragma unroll
            for (int pos = 0; pos < 4; ++pos)
                subt[(pos * 8 + wi) * STH + ch] = __float2half_rn(o[i][pos] * inv);
        }
    }
}

// ---------------------------------------------------------------------------
__global__ void __launch_bounds__(NTH, 3)
wavelet_attn_kernel(const float* __restrict__ x,
                    float* __restrict__ y)
{
    extern __shared__ char smem[];
    __half* subt = (__half*)smem;                       // 32 x STH halves
    __half* qkv  = (__half*)(smem + SUBT_BYTES);        // 384 x QPH halves

    const int tid  = threadIdx.x;
    const int wblk = blockIdx.x;       // 0..7
    const int h    = blockIdx.y;       // 0..63
    const int b    = blockIdx.z;       // 0..7

    const int warp = tid >> 5, lane = tid & 31;
    const int g = lane >> 2, t = lane & 3;

    const int xrow0 = 4 * h;
    const int xcol0 = 32 * wblk;
    const float* xb = x + (size_t)(b * 64) * 65536;

    // -------- phase 0: load x (float4), butterfly DWT -> sub_t --------
    // stores UNHALVED sums (the 0.5 lives in the weight images)
    {
        const int jq = tid & 7;
        const int ch = (tid >> 3) * 2;
        const float* xcA = xb + (size_t)ch * 65536;
        const float* xcB = xcA + 65536;
        const int col = xcol0 + 4 * jq;
#pragma unroll
        for (int dy = 0; dy < 2; ++dy) {
            const int r0 = xrow0 + 2 * dy;
            const float4 tA = *(const float4*)(xcA + r0 * 256 + col);
            const float4 uA = *(const float4*)(xcA + (r0 + 1) * 256 + col);
            const float4 tB = *(const float4*)(xcB + r0 * 256 + col);
            const float4 uB = *(const float4*)(xcB + (r0 + 1) * 256 + col);
#pragma unroll
            for (int dx = 0; dx < 2; ++dx) {
                const float aA = dx ? tA.z : tA.x, bA = dx ? tA.w : tA.y;
                const float cA = dx ? uA.z : uA.x, dA = dx ? uA.w : uA.y;
                const float aB = dx ? tB.z : tB.x, bB = dx ? tB.w : tB.y;
                const float cB = dx ? uB.z : uB.x, dB = dx ? uB.w : uB.y;
                // butterfly: t1=a+b, t2=c+d, t3=b-a, t4=d-c
                const float t1A = aA + bA, t2A = cA + dA;
                const float t3A = bA - aA, t4A = dA - cA;
                const float t1B = aB + bB, t2B = cB + dB;
                const float t3B = bB - aB, t4B = dB - cB;
                const int row = (2 * dy + dx) * 8 + jq;
                __half* sr = &subt[row * STH + ch];
                *(unsigned*)&sr[0]   = pack2(t1A + t2A, t1B + t2B);  // 2*ll
                *(unsigned*)&sr[64]  = pack2(t2A - t1A, t2B - t1B);  // 2*lh
                *(unsigned*)&sr[128] = pack2(t3A + t4A, t3B + t4B);  // 2*hl
                *(unsigned*)&sr[192] = pack2(t4A - t3A, t4B - t3B);  // 2*hh
            }
        }
    }
    __syncthreads();

    // ======== fused LOW+HIGH GEMM (one pass over w_lh fragments) ========
    {
        const int wm = warp >> 1, wn = warp & 1;   // 4x2 warp grid
        float acc[2][3][2][4];
#pragma unroll
        for (int bd = 0; bd < 2; ++bd)
#pragma unroll
            for (int mt = 0; mt < 3; ++mt)
#pragma unroll
                for (int nt = 0; nt < 2; ++nt)
                    acc[bd][mt][nt][0] = acc[bd][mt][nt][1] =
                    acc[bd][mt][nt][2] = acc[bd][mt][nt][3] = 0.f;

#pragma unroll
        for (int kk = 0; kk < 4; ++kk) {
            uint4 af[3];
#pragma unroll
            for (int mt = 0; mt < 3; ++mt)
                af[mt] = g_wfrag_lh[((wm * 3 + mt) * 4 + kk) * 32 + lane];

            unsigned bl[2][2], bh[2][2];
            const int kcol = kk * 16 + 2 * t;
#pragma unroll
            for (int nt = 0; nt < 2; ++nt) {
                const int row = (wn * 2 + nt) * 8 + g;
                const __half* sr = &subt[row * STH + kcol];
                bl[nt][0] = *(const unsigned*)&sr[0];
                bl[nt][1] = *(const unsigned*)&sr[8];
                bh[nt][0] = *(const unsigned*)&sr[192];
                bh[nt][1] = *(const unsigned*)&sr[200];
            }
#pragma unroll
            for (int mt = 0; mt < 3; ++mt)
#pragma unroll
                for (int nt = 0; nt < 2; ++nt) {
                    mma16(acc[0][mt][nt], af[mt], bl[nt][0], bl[nt][1]);
                    mma16(acc[1][mt][nt], af[mt], bh[nt][0], bh[nt][1]);
                }
        }
        // C store (packed half2 across nt)
#pragma unroll
        for (int bd = 0; bd < 2; ++bd)
#pragma unroll
            for (int mt = 0; mt < 3; ++mt) {
                const int m  = bd * 192 + wm * 48 + mt * 16 + g;
                const int p0 = 8 * t + wn * 2;
                stq2(qkv, m,     p0,     acc[bd][mt][0][0], acc[bd][mt][1][0]);
                stq2(qkv, m,     p0 + 4, acc[bd][mt][0][1], acc[bd][mt][1][1]);
                stq2(qkv, m + 8, p0,     acc[bd][mt][0][2], acc[bd][mt][1][2]);
                stq2(qkv, m + 8, p0 + 4, acc[bd][mt][0][3], acc[bd][mt][1][3]);
            }
        __syncthreads();

        attn_lh(qkv, subt, warp, lane);    // all heads, both bands
        // NO barrier here: mid-GEMM mainloop below reads subt cols 64..192
        // only (disjoint from attn_lh's writes to cols 0..64 / 192..256);
        // the qkv WAR hazard is guarded by the barrier before the C-store.
    }

    // ======== MID GEMM: w_m @ sub_t[:, 64..192) ========
    {
        float acc[3][4][4];
#pragma unroll
        for (int mt = 0; mt < 3; ++mt)
#pragma unroll
            for (int nt = 0; nt < 4; ++nt)
                acc[mt][nt][0] = acc[mt][nt][1] = acc[mt][nt][2] = acc[mt][nt][3] = 0.f;

#pragma unroll
        for (int kk = 0; kk < 8; ++kk) {
            uint4 af[3];
#pragma unroll
            for (int mt = 0; mt < 3; ++mt)
                af[mt] = g_wfrag_m[((warp * 3 + mt) * 8 + kk) * 32 + lane];

            unsigned bf[4][2];
            const int kcol = 64 + kk * 16 + 2 * t;
#pragma unroll
            for (int nt = 0; nt < 4; ++nt) {
                const __half* sr = &subt[(nt * 8 + g) * STH + kcol];
                bf[nt][0] = *(const unsigned*)&sr[0];
                bf[nt][1] = *(const unsigned*)&sr[8];
            }
#pragma unroll
            for (int mt = 0; mt < 3; ++mt)
#pragma unroll
                for (int nt = 0; nt < 4; ++nt)
                    mma16(acc[mt][nt], af[mt], bf[nt][0], bf[nt][1]);
        }
        __syncthreads();   // all warps done reading qkv (attn_lh) -> C-store

        // C store (packed half2): pos blocks 8t..8t+3 (c0/c1) and 8t+4..8t+7
#pragma unroll
        for (int mt = 0; mt < 3; ++mt) {
            const int m  = warp * 48 + mt * 16 + g;
            const int p0 = 8 * t;
            stq2(qkv, m,     p0,     acc[mt][0][0], acc[mt][1][0]);
            stq2(qkv, m,     p0 + 2, acc[mt][2][0], acc[mt][3][0]);
            stq2(qkv, m,     p0 + 4, acc[mt][0][1], acc[mt][1][1]);
            stq2(qkv, m,     p0 + 6, acc[mt][2][1], acc[mt][3][1]);
            stq2(qkv, m + 8, p0,     acc[mt][0][2], acc[mt][1][2]);
            stq2(qkv, m + 8, p0 + 2, acc[mt][2][2], acc[mt][3][2]);
            stq2(qkv, m + 8, p0 + 4, acc[mt][0][3], acc[mt][1][3]);
            stq2(qkv, m + 8, p0 + 6, acc[mt][2][3], acc[mt][3][3]);
        }
        __syncthreads();

        attn_mid(qkv, subt, warp, lane);   // all heads
        __syncthreads();
    }

    // -------- phase 4: butterfly IDWT from sub_t (fp16) -> y --------
    {
        const int jq = tid & 7;
        const int ch = (tid >> 3) * 2;
        float* ycA = y + (size_t)(b * 64 + ch) * 65536;
        float* ycB = ycA + 65536;
        const int col = xcol0 + 4 * jq;
#pragma unroll
        for (int dy = 0; dy < 2; ++dy) {
            float topA[4], botA[4], topB[4], botB[4];
#pragma unroll
            for (int dx = 0; dx < 2; ++dx) {
                const int row = (2 * dy + dx) * 8 + jq;
                const __half* sr = &subt[row * STH + ch];
                const float2 ll = __half22float2(*(const __half2*)&sr[0]);
                const float2 lh = __half22float2(*(const __half2*)&sr[64]);
                const float2 hl = __half22float2(*(const __half2*)&sr[128]);
                const float2 hh = __half22float2(*(const __half2*)&sr[192]);
                // butterfly: u=ll+hh, w=lh+hl, v=ll-hh, z=hl-lh
                const float uA = ll.x + hh.x, wA = lh.x + hl.x;
                const float vA = ll.x - hh.x, zA = hl.x - lh.x;
                const float uB = ll.y + hh.y, wB = lh.y + hl.y;
                const float vB = ll.y - hh.y, zB = hl.y - lh.y;
                topA[2 * dx]     = (uA - wA) * 0.5f;   // a
                topA[2 * dx + 1] = (vA + zA) * 0.5f;   // b
                botA[2 * dx]     = (vA - zA) * 0.5f;   // c
                botA[2 * dx + 1] = (uA + wA) * 0.5f;   // d
                topB[2 * dx]     = (uB - wB) * 0.5f;
                topB[2 * dx + 1] = (vB + zB) * 0.5f;
                botB[2 * dx]     = (vB - zB) * 0.5f;
                botB[2 * dx + 1] = (uB + wB) * 0.5f;
            }
            const int r0 = xrow0 + 2 * dy;
            *(float4*)(ycA + r0 * 256 + col)       = make_float4(topA[0], topA[1], topA[2], topA[3]);
            *(float4*)(ycA + (r0 + 1) * 256 + col) = make_float4(botA[0], botA[1], botA[2], botA[3]);
            *(float4*)(ycB + r0 * 256 + col)       = make_float4(topB[0], topB[1], topB[2], topB[3]);
            *(float4*)(ycB + (r0 + 1) * 256 + col) = make_float4(botB[0], botB[1], botB[2], botB[3]);
        }
    }
}

// ---------------------------------------------------------------------------
extern "C" void kernel_launch(void* const* d_in, const int* in_sizes, int n_in,
                              void* d_out, int out_size)
{
    (void)in_sizes; (void)n_in; (void)out_size;
    const float* x    = (const float*)d_in[0];
    const float* w_lh = (const float*)d_in[1];
    const float* w_m  = (const float*)d_in[2];
    float* y = (float*)d_out;

    cudaFuncSetAttribute(wavelet_attn_kernel,
                         cudaFuncAttributeMaxDynamicSharedMemorySize, SMEM_BYTES);

    prep_weights<<<30, 256>>>(w_lh, w_m);

    dim3 grid(8, 64, 8);   // wblk, h, b -> 4096 CTAs
    wavelet_attn_kernel<<<grid, NTH, SMEM_BYTES>>>(x, y);
}

// round 16
// speedup vs baseline: 1.6117x; 1.2666x over previous
#include <cuda_runtime.h>
#include <cuda_fp16.h>
#include <math.h>

// ---------------------------------------------------------------------------
// Fused Haar-DWT -> conv1x1 QKV (fp16 mma, fp32 accum) -> 2x2-window
// channel-attention -> Haar-IDWT.
// x (8,64,256,256) f32; w_qkv_lh (192,64); w_qkv_m (384,128).
//
// R16: TENSOR-CORE MID ATTENTION. Per (window, head):
//   S = Q K^T via 8x mma.m16n8k8.f16 (s padded 4->8, predicated-zero frags),
//   p = ex2(S) elementwise on fp32 C-frags, packed fp16 -> PV A-frags
//   (C layout of m16n8 == A layout of m16n8k16, no SMEM round trip),
//   O = P @ Vaug via 4x mma.m16n8k16 with Vaug col4 = ones -> softmax sum
//   drops out of the same mma (O col 4). One shuffle broadcasts sums.
// lh attention stays scalar (R12/R14 form). All R13-R15 structure retained.
// 44.5 KB SMEM, 256 threads, 3 CTAs/SM.
// ---------------------------------------------------------------------------

#define NTH  256
#define STH  264            // sub_t row stride (halves); 132 words == 4 mod 32
#define QPH  36             // qkv row stride (halves, 72B)

#define SUBT_BYTES  (32 * STH * 2)          // 16896
#define QKV_BYTES   (384 * QPH * 2)         // 27648
#define SMEM_BYTES  (SUBT_BYTES + QKV_BYTES)   // 44544

// fp16 qkv swizzle: xor 0 or 4 halves (8B) by row bit6
#define QSW(row)        ((((row) >> 6) & 1) << 2)
#define QIDXH(row, pos) ((row) * QPH + ((pos) ^ QSW(row)))

// fragment-ordered fp16 weight images: tile(M16,K16) x 32 lanes x uint4
__device__ uint4 g_wfrag_lh[12 * 4 * 32];
__device__ uint4 g_wfrag_m [24 * 8 * 32];

__device__ __forceinline__ unsigned pack2(float a, float b) {
    __half2 h = __floats2half2_rn(a, b);   // .x (low) = a
    return *(unsigned*)&h;
}
__device__ __forceinline__ unsigned packh2(__half lo, __half hi) {
    return (unsigned)__half_as_ushort(lo) | ((unsigned)__half_as_ushort(hi) << 16);
}
__device__ __forceinline__ float ex2f(float x) {
    float r; asm("ex2.approx.ftz.f32 %0, %1;" : "=f"(r) : "f"(x)); return r;
}
__device__ __forceinline__ float rcpf(float x) {
    float r; asm("rcp.approx.ftz.f32 %0, %1;" : "=f"(r) : "f"(x)); return r;
}
// 8-byte fp16 vector -> float4
__device__ __forceinline__ float4 h2f4(uint2 u) {
    const float2 a = __half22float2(*(const __half2*)&u.x);
    const float2 b = __half22float2(*(const __half2*)&u.y);
    return make_float4(a.x, a.y, b.x, b.y);
}
// packed half2 store at logical (row, pos) = values (pos, pos+1)
__device__ __forceinline__ void stq2(__half* qkv, int row, int pos, float a, float b) {
    *(unsigned*)&qkv[QIDXH(row, pos)] = pack2(a, b);
}

// scale * log2(e)
#define SC2_LH  0.36067376022224085f   // 0.25      * log2(e)
#define SC2_M   0.25505003980080184f   // 0.1767767 * log2(e)

// D += A(16x16,row) * B(16x8,col), fp16 in, fp32 accum
__device__ __forceinline__ void mma16(float* d, const uint4 a, unsigned b0, unsigned b1) {
    asm volatile(
        "mma.sync.aligned.m16n8k16.row.col.f32.f16.f16.f32 "
        "{%0,%1,%2,%3}, {%4,%5,%6,%7}, {%8,%9}, {%0,%1,%2,%3};"
        : "+f"(d[0]), "+f"(d[1]), "+f"(d[2]), "+f"(d[3])
        : "r"(a.x), "r"(a.y), "r"(a.z), "r"(a.w), "r"(b0), "r"(b1));
}
// D += A(16x8,row) * B(8x8,col), fp16 in, fp32 accum
__device__ __forceinline__ void mma8h(float* d, unsigned a0, unsigned a1, unsigned b0) {
    asm volatile(
        "mma.sync.aligned.m16n8k8.row.col.f32.f16.f16.f32 "
        "{%0,%1,%2,%3}, {%4,%5}, {%6}, {%0,%1,%2,%3};"
        : "+f"(d[0]), "+f"(d[1]), "+f"(d[2]), "+f"(d[3])
        : "r"(a0), "r"(a1), "r"(b0));
}

// ---------------------------------------------------------------------------
// prep: fragment-order the weights in fp16.
// ALL rows carry the DWT 0.5; q-rows additionally carry scale*log2e.
// ---------------------------------------------------------------------------
__global__ void prep_weights(const float* __restrict__ w_lh,
                             const float* __restrict__ w_m)
{
    const int i = blockIdx.x * blockDim.x + threadIdx.x;
    const int lane = i & 31;
    const int g = lane >> 2, t = lane & 3;
    if (i < 12 * 4 * 32) {
        const int T = i >> 5;
        const int kk = T & 3, mt = T >> 2;
        const int m = mt * 16 + g, k = kk * 16 + 2 * t;
        const float s = (m < 64) ? (SC2_LH * 0.5f) : 0.5f;
        uint4 v;
        v.x = pack2(s * w_lh[m * 64 + k],           s * w_lh[m * 64 + k + 1]);
        v.y = pack2(s * w_lh[(m + 8) * 64 + k],     s * w_lh[(m + 8) * 64 + k + 1]);
        v.z = pack2(s * w_lh[m * 64 + k + 8],       s * w_lh[m * 64 + k + 9]);
        v.w = pack2(s * w_lh[(m + 8) * 64 + k + 8], s * w_lh[(m + 8) * 64 + k + 9]);
        g_wfrag_lh[T * 32 + lane] = v;
    } else {
        const int j = i - 12 * 4 * 32;
        if (j < 24 * 8 * 32) {
            const int T = j >> 5;
            const int kk = T & 7, mt = T >> 3;
            const int m = mt * 16 + g, k = kk * 16 + 2 * t;
            const float s = (m < 128) ? (SC2_M * 0.5f) : 0.5f;
            uint4 v;
            v.x = pack2(s * w_m[m * 128 + k],           s * w_m[m * 128 + k + 1]);
            v.y = pack2(s * w_m[(m + 8) * 128 + k],     s * w_m[(m + 8) * 128 + k + 1]);
            v.z = pack2(s * w_m[m * 128 + k + 8],       s * w_m[m * 128 + k + 9]);
            v.w = pack2(s * w_m[(m + 8) * 128 + k + 8], s * w_m[(m + 8) * 128 + k + 9]);
            g_wfrag_m[T * 32 + lane] = v;
        }
    }
}

// ---------------------------------------------------------------------------
// low+high attention (scalar, R14 form). lane = (band, head, j).
// ---------------------------------------------------------------------------
__device__ __forceinline__ void attn_lh(
    const __half* __restrict__ qkv, __half* __restrict__ subt,
    int wi, int lane)
{
    const int c0   = wi * 4;
    const int band = lane >> 4;
    const int qb   = band * 192;
    const int hd   = (lane >> 2) & 3;
    const int j    = lane & 3;
    const int cQ   = band ? (c0 ^ 4) : c0;
    const int cK   = band ? c0 : (c0 ^ 4);
    const int cV   = band ? (c0 ^ 4) : c0;

#pragma unroll 1
    for (int ps = 0; ps < 2; ++ps) {
        float4 q[2];
#pragma unroll
        for (int i = 0; i < 2; ++i) {
            const int row = qb + (j + 4 * (2 * ps + i)) * 4 + hd;
            q[i] = h2f4(*(const uint2*)&qkv[row * QPH + cQ]);
        }
        float sm[2] = {0.f, 0.f};
        float o[2][4];
#pragma unroll
        for (int i = 0; i < 2; ++i)
            o[i][0] = o[i][1] = o[i][2] = o[i][3] = 0.f;

        const __half* pk = &qkv[(qb + 64  + hd) * QPH + cK];
        const __half* pv = &qkv[(qb + 128 + hd) * QPH + cV];
#pragma unroll 4
        for (int d = 0; d < 16; ++d) {
            const float4 k4 = h2f4(*(const uint2*)pk); pk += 4 * QPH;
            const float4 v4 = h2f4(*(const uint2*)pv); pv += 4 * QPH;
#pragma unroll
            for (int i = 0; i < 2; ++i) {
                const float p = ex2f(q[i].x * k4.x + q[i].y * k4.y +
                                     q[i].z * k4.z + q[i].w * k4.w);
                sm[i] += p;
                o[i][0] = fmaf(p, v4.x, o[i][0]);
                o[i][1] = fmaf(p, v4.y, o[i][1]);
                o[i][2] = fmaf(p, v4.z, o[i][2]);
                o[i][3] = fmaf(p, v4.w, o[i][3]);
            }
        }
#pragma unroll
        for (int i = 0; i < 2; ++i) {
            const float inv = rcpf(sm[i]);
            const int ch = qb + (j + 4 * (2 * ps + i)) * 4 + hd;
#pragma unroll
            for (int pos = 0; pos < 4; ++pos)
                subt[(pos * 8 + wi) * STH + ch] = __float2half_rn(o[i][pos] * inv);
        }
    }
}

// ---------------------------------------------------------------------------
// mid attention on tensor cores. Warp = window; loop over 4 heads.
//  S[c,d] (32x32, K=s padded 4->8):  8x mma.m16n8k8
//  p = ex2(S) elementwise; P fp16 frags feed PV directly (C==A layout).
//  O = P @ Vaug (Vaug cols: v0..v3, ones, 0,0,0): 4x mma.m16n8k16.
//  O col 4 = softmax sum -> shuffle-broadcast, normalize, store to subt.
// Row-bit6 swizzle is constant per fragment group (Q: mt; K: nt>=2; V: kc).
// ---------------------------------------------------------------------------
__device__ __forceinline__ void attn_mid_tc(
    const __half* __restrict__ qkv, __half* __restrict__ subt,
    int wi, int lane)
{
    const int g = lane >> 2, t = lane & 3;
    const int p0 = wi * 4;
    const unsigned ONE2 = 0x3C003C00u;      // half2(1,1)

#pragma unroll 1
    for (int hd = 0; hd < 4; ++hd) {
        // ---- S = Q K^T ----
        unsigned aq[2][2], bk[4];
#pragma unroll
        for (int mt = 0; mt < 2; ++mt) {
            const int col = (p0 + 2 * t) ^ (mt ? 4 : 0);
            const int c = mt * 16 + g;
            aq[mt][0] = (t < 2) ? *(const unsigned*)&qkv[(c * 4 + hd) * QPH + col] : 0u;
            aq[mt][1] = (t < 2) ? *(const unsigned*)&qkv[((c + 8) * 4 + hd) * QPH + col] : 0u;
        }
#pragma unroll
        for (int nt = 0; nt < 4; ++nt) {
            const int col = (p0 + 2 * t) ^ ((nt >= 2) ? 4 : 0);
            const int d = nt * 8 + g;
            bk[nt] = (t < 2) ? *(const unsigned*)&qkv[(128 + d * 4 + hd) * QPH + col] : 0u;
        }
        float s[2][4][4];
#pragma unroll
        for (int mt = 0; mt < 2; ++mt)
#pragma unroll
            for (int nt = 0; nt < 4; ++nt) {
                s[mt][nt][0] = s[mt][nt][1] = s[mt][nt][2] = s[mt][nt][3] = 0.f;
                mma8h(s[mt][nt], aq[mt][0], aq[mt][1], bk[nt]);
            }

        // ---- p = ex2(S), pack into PV A-frags ----
        uint4 pa[2][2];     // [mt][kc]
#pragma unroll
        for (int mt = 0; mt < 2; ++mt)
#pragma unroll
            for (int kc = 0; kc < 2; ++kc) {
                pa[mt][kc].x = pack2(ex2f(s[mt][2*kc][0]),   ex2f(s[mt][2*kc][1]));
                pa[mt][kc].y = pack2(ex2f(s[mt][2*kc][2]),   ex2f(s[mt][2*kc][3]));
                pa[mt][kc].z = pack2(ex2f(s[mt][2*kc+1][0]), ex2f(s[mt][2*kc+1][1]));
                pa[mt][kc].w = pack2(ex2f(s[mt][2*kc+1][2]), ex2f(s[mt][2*kc+1][3]));
            }

        // ---- Vaug B-frags ----
        unsigned bv[2][2];  // [kc][b0,b1]
#pragma unroll
        for (int kc = 0; kc < 2; ++kc) {
            const int col = (p0 + g) ^ (kc ? 4 : 0);
            const int rbase = 256 + (kc * 16) * 4 + hd;
            if (g < 4) {
                const int r0 = rbase + (2 * t) * 4;        // d = kc*16 + 2t
                bv[kc][0] = packh2(qkv[r0 * QPH + col],
                                   qkv[(r0 + 4) * QPH + col]);
                const int r8 = rbase + (2 * t + 8) * 4;    // d = kc*16 + 2t+8
                bv[kc][1] = packh2(qkv[r8 * QPH + col],
                                   qkv[(r8 + 4) * QPH + col]);
            } else if (g == 4) {
                bv[kc][0] = ONE2; bv[kc][1] = ONE2;
            } else {
                bv[kc][0] = 0u;   bv[kc][1] = 0u;
            }
        }

        // ---- O = P @ Vaug ----
        float o[2][4];
#pragma unroll
        for (int mt = 0; mt < 2; ++mt) {
            o[mt][0] = o[mt][1] = o[mt][2] = o[mt][3] = 0.f;
#pragma unroll
            for (int kc = 0; kc < 2; ++kc)
                mma16(o[mt], pa[mt][kc], bv[kc][0], bv[kc][1]);
        }

        // ---- normalize (sum lives at col 4 = lanes t==2) and store ----
        const int src = (lane & 0x1C) | 2;
#pragma unroll
        for (int mt = 0; mt < 2; ++mt) {
            const float sum0 = __shfl_sync(0xffffffffu, o[mt][0], src);
            const float sum1 = __shfl_sync(0xffffffffu, o[mt][2], src);
            const float i0 = rcpf(sum0);
            const float i1 = rcpf(sum1);
            if (t < 2) {
                const int ch0 = 64 + (mt * 16 + g) * 4 + hd;
                const int ch8 = ch0 + 32;
                subt[((2*t)   * 8 + wi) * STH + ch0] = __float2half_rn(o[mt][0] * i0);
                subt[((2*t+1) * 8 + wi) * STH + ch0] = __float2half_rn(o[mt][1] * i0);
                subt[((2*t)   * 8 + wi) * STH + ch8] = __float2half_rn(o[mt][2] * i1);
                subt[((2*t+1) * 8 + wi) * STH + ch8] = __float2half_rn(o[mt][3] * i1);
            }
        }
    }
}

// ---------------------------------------------------------------------------
__global__ void __launch_bounds__(NTH, 3)
wavelet_attn_kernel(const float* __restrict__ x,
                    float* __restrict__ y)
{
    extern __shared__ char smem[];
    __half* subt = (__half*)smem;                       // 32 x STH halves
    __half* qkv  = (__half*)(smem + SUBT_BYTES);        // 384 x QPH halves

    const int tid  = threadIdx.x;
    const int wblk = blockIdx.x;       // 0..7
    const int h    = blockIdx.y;       // 0..63
    const int b    = blockIdx.z;       // 0..7

    const int warp = tid >> 5, lane = tid & 31;
    const int g = lane >> 2, t = lane & 3;

    const int xrow0 = 4 * h;
    const int xcol0 = 32 * wblk;
    const float* xb = x + (size_t)(b * 64) * 65536;

    // -------- phase 0: load x (float4), butterfly DWT -> sub_t --------
    {
        const int jq = tid & 7;
        const int ch = (tid >> 3) * 2;
        const float* xcA = xb + (size_t)ch * 65536;
        const float* xcB = xcA + 65536;
        const int col = xcol0 + 4 * jq;
#pragma unroll
        for (int dy = 0; dy < 2; ++dy) {
            const int r0 = xrow0 + 2 * dy;
            const float4 tA = *(const float4*)(xcA + r0 * 256 + col);
            const float4 uA = *(const float4*)(xcA + (r0 + 1) * 256 + col);
            const float4 tB = *(const float4*)(xcB + r0 * 256 + col);
            const float4 uB = *(const float4*)(xcB + (r0 + 1) * 256 + col);
#pragma unroll
            for (int dx = 0; dx < 2; ++dx) {
                const float aA = dx ? tA.z : tA.x, bA = dx ? tA.w : tA.y;
                const float cA = dx ? uA.z : uA.x, dA = dx ? uA.w : uA.y;
                const float aB = dx ? tB.z : tB.x, bB = dx ? tB.w : tB.y;
                const float cB = dx ? uB.z : uB.x, dB = dx ? uB.w : uB.y;
                const float t1A = aA + bA, t2A = cA + dA;
                const float t3A = bA - aA, t4A = dA - cA;
                const float t1B = aB + bB, t2B = cB + dB;
                const float t3B = bB - aB, t4B = dB - cB;
                const int row = (2 * dy + dx) * 8 + jq;
                __half* sr = &subt[row * STH + ch];
                *(unsigned*)&sr[0]   = pack2(t1A + t2A, t1B + t2B);  // 2*ll
                *(unsigned*)&sr[64]  = pack2(t2A - t1A, t2B - t1B);  // 2*lh
                *(unsigned*)&sr[128] = pack2(t3A + t4A, t3B + t4B);  // 2*hl
                *(unsigned*)&sr[192] = pack2(t4A - t3A, t4B - t3B);  // 2*hh
            }
        }
    }
    __syncthreads();

    // ======== fused LOW+HIGH GEMM (one pass over w_lh fragments) ========
    {
        const int wm = warp >> 1, wn = warp & 1;
        float acc[2][3][2][4];
#pragma unroll
        for (int bd = 0; bd < 2; ++bd)
#pragma unroll
            for (int mt = 0; mt < 3; ++mt)
#pragma unroll
                for (int nt = 0; nt < 2; ++nt)
                    acc[bd][mt][nt][0] = acc[bd][mt][nt][1] =
                    acc[bd][mt][nt][2] = acc[bd][mt][nt][3] = 0.f;

#pragma unroll
        for (int kk = 0; kk < 4; ++kk) {
            uint4 af[3];
#pragma unroll
            for (int mt = 0; mt < 3; ++mt)
                af[mt] = g_wfrag_lh[((wm * 3 + mt) * 4 + kk) * 32 + lane];

            unsigned bl[2][2], bh[2][2];
            const int kcol = kk * 16 + 2 * t;
#pragma unroll
            for (int nt = 0; nt < 2; ++nt) {
                const int row = (wn * 2 + nt) * 8 + g;
                const __half* sr = &subt[row * STH + kcol];
                bl[nt][0] = *(const unsigned*)&sr[0];
                bl[nt][1] = *(const unsigned*)&sr[8];
                bh[nt][0] = *(const unsigned*)&sr[192];
                bh[nt][1] = *(const unsigned*)&sr[200];
            }
#pragma unroll
            for (int mt = 0; mt < 3; ++mt)
#pragma unroll
                for (int nt = 0; nt < 2; ++nt) {
                    mma16(acc[0][mt][nt], af[mt], bl[nt][0], bl[nt][1]);
                    mma16(acc[1][mt][nt], af[mt], bh[nt][0], bh[nt][1]);
                }
        }
#pragma unroll
        for (int bd = 0; bd < 2; ++bd)
#pragma unroll
            for (int mt = 0; mt < 3; ++mt) {
                const int m  = bd * 192 + wm * 48 + mt * 16 + g;
                const int p0 = 8 * t + wn * 2;
                stq2(qkv, m,     p0,     acc[bd][mt][0][0], acc[bd][mt][1][0]);
                stq2(qkv, m,     p0 + 4, acc[bd][mt][0][1], acc[bd][mt][1][1]);
                stq2(qkv, m + 8, p0,     acc[bd][mt][0][2], acc[bd][mt][1][2]);
                stq2(qkv, m + 8, p0 + 4, acc[bd][mt][0][3], acc[bd][mt][1][3]);
            }
        __syncthreads();

        attn_lh(qkv, subt, warp, lane);    // all heads, both bands
        // no barrier: mid mainloop reads subt cols 64..192 (disjoint);
        // qkv WAR guarded by the barrier before the mid C-store.
    }

    // ======== MID GEMM: w_m @ sub_t[:, 64..192) ========
    {
        float acc[3][4][4];
#pragma unroll
        for (int mt = 0; mt < 3; ++mt)
#pragma unroll
            for (int nt = 0; nt < 4; ++nt)
                acc[mt][nt][0] = acc[mt][nt][1] = acc[mt][nt][2] = acc[mt][nt][3] = 0.f;

#pragma unroll
        for (int kk = 0; kk < 8; ++kk) {
            uint4 af[3];
#pragma unroll
            for (int mt = 0; mt < 3; ++mt)
                af[mt] = g_wfrag_m[((warp * 3 + mt) * 8 + kk) * 32 + lane];

            unsigned bf[4][2];
            const int kcol = 64 + kk * 16 + 2 * t;
#pragma unroll
            for (int nt = 0; nt < 4; ++nt) {
                const __half* sr = &subt[(nt * 8 + g) * STH + kcol];
                bf[nt][0] = *(const unsigned*)&sr[0];
                bf[nt][1] = *(const unsigned*)&sr[8];
            }
#pragma unroll
            for (int mt = 0; mt < 3; ++mt)
#pragma unroll
                for (int nt = 0; nt < 4; ++nt)
                    mma16(acc[mt][nt], af[mt], bf[nt][0], bf[nt][1]);
        }
        __syncthreads();   // all warps done reading qkv (attn_lh) -> C-store

#pragma unroll
        for (int mt = 0; mt < 3; ++mt) {
            const int m  = warp * 48 + mt * 16 + g;
            const int p0 = 8 * t;
            stq2(qkv, m,     p0,     acc[mt][0][0], acc[mt][1][0]);
            stq2(qkv, m,     p0 + 2, acc[mt][2][0], acc[mt][3][0]);
            stq2(qkv, m,     p0 + 4, acc[mt][0][1], acc[mt][1][1]);
            stq2(qkv, m,     p0 + 6, acc[mt][2][1], acc[mt][3][1]);
            stq2(qkv, m + 8, p0,     acc[mt][0][2], acc[mt][1][2]);
            stq2(qkv, m + 8, p0 + 2, acc[mt][2][2], acc[mt][3][2]);
            stq2(qkv, m + 8, p0 + 4, acc[mt][0][3], acc[mt][1][3]);
            stq2(qkv, m + 8, p0 + 6, acc[mt][2][3], acc[mt][3][3]);
        }
        __syncthreads();

        attn_mid_tc(qkv, subt, warp, lane);   // tensor-core, all heads
        __syncthreads();
    }

    // -------- phase 4: butterfly IDWT from sub_t (fp16) -> y --------
    {
        const int jq = tid & 7;
        const int ch = (tid >> 3) * 2;
        float* ycA = y + (size_t)(b * 64 + ch) * 65536;
        float* ycB = ycA + 65536;
        const int col = xcol0 + 4 * jq;
#pragma unroll
        for (int dy = 0; dy < 2; ++dy) {
            float topA[4], botA[4], topB[4], botB[4];
#pragma unroll
            for (int dx = 0; dx < 2; ++dx) {
                const int row = (2 * dy + dx) * 8 + jq;
                const __half* sr = &subt[row * STH + ch];
                const float2 ll = __half22float2(*(const __half2*)&sr[0]);
                const float2 lh = __half22float2(*(const __half2*)&sr[64]);
                const float2 hl = __half22float2(*(const __half2*)&sr[128]);
                const float2 hh = __half22float2(*(const __half2*)&sr[192]);
                const float uA = ll.x + hh.x, wA = lh.x + hl.x;
                const float vA = ll.x - hh.x, zA = hl.x - lh.x;
                const float uB = ll.y + hh.y, wB = lh.y + hl.y;
                const float vB = ll.y - hh.y, zB = hl.y - lh.y;
                topA[2 * dx]     = (uA - wA) * 0.5f;
                topA[2 * dx + 1] = (vA + zA) * 0.5f;
                botA[2 * dx]     = (vA - zA) * 0.5f;
                botA[2 * dx + 1] = (uA + wA) * 0.5f;
                topB[2 * dx]     = (uB - wB) * 0.5f;
                topB[2 * dx + 1] = (vB + zB) * 0.5f;
                botB[2 * dx]     = (vB - zB) * 0.5f;
                botB[2 * dx + 1] = (uB + wB) * 0.5f;
            }
            const int r0 = xrow0 + 2 * dy;
            *(float4*)(ycA + r0 * 256 + col)       = make_float4(topA[0], topA[1], topA[2], topA[3]);
            *(float4*)(ycA + (r0 + 1) * 256 + col) = make_float4(botA[0], botA[1], botA[2], botA[3]);
            *(float4*)(ycB + r0 * 256 + col)       = make_float4(topB[0], topB[1], topB[2], topB[3]);
            *(float4*)(ycB + (r0 + 1) * 256 + col) = make_float4(botB[0], botB[1], botB[2], botB[3]);
        }
    }
}

// ---------------------------------------------------------------------------
extern "C" void kernel_launch(void* const* d_in, const int* in_sizes, int n_in,
                              void* d_out, int out_size)
{
    (void)in_sizes; (void)n_in; (void)out_size;
    const float* x    = (const float*)d_in[0];
    const float* w_lh = (const float*)d_in[1];
    const float* w_m  = (const float*)d_in[2];
    float* y = (float*)d_out;

    cudaFuncSetAttribute(wavelet_attn_kernel,
                         cudaFuncAttributeMaxDynamicSharedMemorySize, SMEM_BYTES);

    prep_weights<<<30, 256>>>(w_lh, w_m);

    dim3 grid(8, 64, 8);   // wblk, h, b -> 4096 CTAs
    wavelet_attn_kernel<<<grid, NTH, SMEM_BYTES>>>(x, y);
}